// round 1
// baseline (speedup 1.0000x reference)
#include <cuda_runtime.h>
#include <math.h>

#define B_ 4
#define N_ 1024
#define M_ 1024
#define D_ 512
#define EPS_F 0.1f
#define INV_EPS 10.0f
#define THRESH_F 0.1f
// ln(1/1024 + 1e-8)
#define LOG_MU -6.9314616f
#define MU_VAL (1.0f/1024.0f + 1e-8f)

// ---------------- scratch (no runtime allocation allowed) ----------------
__device__ float g_E [B_*N_*M_];   // exp(-C/eps), row-major [b][i][j]
__device__ float g_ET[B_*M_*N_];   // transpose     [b][j][i]
__device__ float g_nx[B_*N_];
__device__ float g_ny[B_*M_];
__device__ float g_u  [B_*N_];     // u (log domain), for err only
__device__ float g_aexp[B_*N_];    // exp(u/eps)
__device__ float g_bexp[B_*M_];    // exp(v/eps)
__device__ float g_errbuf[B_*N_];
__device__ float g_rowsum[B_*N_];
__device__ int   g_done;

// ---------------- row norms ----------------
__global__ void norm_x_kernel(const float* __restrict__ v) {
    int row = blockIdx.x;            // 0..4095
    int t = threadIdx.x;             // 128
    const float4* p = (const float4*)(v + (size_t)row * D_);
    float4 a = p[t];
    float s = a.x*a.x + a.y*a.y + a.z*a.z + a.w*a.w;
    #pragma unroll
    for (int o = 16; o; o >>= 1) s += __shfl_down_sync(0xffffffffu, s, o);
    __shared__ float ws[4];
    if ((t & 31) == 0) ws[t >> 5] = s;
    __syncthreads();
    if (t == 0) g_nx[row] = sqrtf(ws[0] + ws[1] + ws[2] + ws[3]);
}

__global__ void norm_y_kernel(const float* __restrict__ v) {
    int row = blockIdx.x;
    int t = threadIdx.x;
    const float4* p = (const float4*)(v + (size_t)row * D_);
    float4 a = p[t];
    float s = a.x*a.x + a.y*a.y + a.z*a.z + a.w*a.w;
    #pragma unroll
    for (int o = 16; o; o >>= 1) s += __shfl_down_sync(0xffffffffu, s, o);
    __shared__ float ws[4];
    if ((t & 31) == 0) ws[t >> 5] = s;
    __syncthreads();
    if (t == 0) g_ny[row] = sqrtf(ws[0] + ws[1] + ws[2] + ws[3]);
}

// ---------------- state init ----------------
__global__ void init_kernel() {
    int i = blockIdx.x * 256 + threadIdx.x;
    if (i < B_*M_) { g_bexp[i] = 1.0f; g_u[i] = 0.0f; }
    if (i == 0) g_done = 0;
}

// ---------------- cost GEMM + exp epilogue: g_E = exp(-(1 - dot/denom)/eps) --
__global__ __launch_bounds__(256, 2)
void gemm_exp_kernel(const float* __restrict__ x, const float* __restrict__ y) {
    __shared__ float As[8][128];
    __shared__ float Bs[8][128];
    int b  = blockIdx.z;
    int i0 = blockIdx.y * 128;
    int j0 = blockIdx.x * 128;
    int tid = threadIdx.x;
    int tx = tid & 15, ty = tid >> 4;

    const float* A  = x + (size_t)b * N_ * D_;
    const float* Bp = y + (size_t)b * M_ * D_;

    int lr = tid >> 1;           // 0..127
    int lk = (tid & 1) * 4;      // 0 or 4
    const float* aptr = A  + (size_t)(i0 + lr) * D_ + lk;
    const float* bptr = Bp + (size_t)(j0 + lr) * D_ + lk;

    float acc[8][8] = {};
    float4 av = *(const float4*)aptr;
    float4 bv = *(const float4*)bptr;

    for (int k0 = 0; k0 < D_; k0 += 8) {
        As[lk+0][lr]=av.x; As[lk+1][lr]=av.y; As[lk+2][lr]=av.z; As[lk+3][lr]=av.w;
        Bs[lk+0][lr]=bv.x; Bs[lk+1][lr]=bv.y; Bs[lk+2][lr]=bv.z; Bs[lk+3][lr]=bv.w;
        __syncthreads();
        if (k0 + 8 < D_) {
            av = *(const float4*)(aptr + k0 + 8);
            bv = *(const float4*)(bptr + k0 + 8);
        }
        #pragma unroll
        for (int kk = 0; kk < 8; kk++) {
            float ar[8], br[8];
            #pragma unroll
            for (int q = 0; q < 8; q++) { ar[q] = As[kk][ty*8+q]; br[q] = Bs[kk][tx*8+q]; }
            #pragma unroll
            for (int ii = 0; ii < 8; ii++)
                #pragma unroll
                for (int jj = 0; jj < 8; jj++)
                    acc[ii][jj] = fmaf(ar[ii], br[jj], acc[ii][jj]);
        }
        __syncthreads();
    }

    float nyv[8];
    #pragma unroll
    for (int jj = 0; jj < 8; jj++) nyv[jj] = g_ny[b*M_ + j0 + tx*8 + jj];
    #pragma unroll
    for (int ii = 0; ii < 8; ii++) {
        int gi = i0 + ty*8 + ii;
        float nxv = g_nx[b*N_ + gi];
        float ev[8];
        #pragma unroll
        for (int jj = 0; jj < 8; jj++) {
            float denom = fmaxf(nxv * nyv[jj], 1e-8f);
            float Cv = 1.0f - acc[ii][jj] / denom;
            ev[jj] = __expf(-Cv * INV_EPS);
        }
        float* erow = g_E + ((size_t)b*N_ + gi) * M_ + j0 + tx*8;
        *(float4*)(erow    ) = make_float4(ev[0], ev[1], ev[2], ev[3]);
        *(float4*)(erow + 4) = make_float4(ev[4], ev[5], ev[6], ev[7]);
    }
}

// ---------------- transpose E -> ET ----------------
__global__ void transpose_kernel() {
    __shared__ float tile[32][33];
    int b = blockIdx.z;
    int x0 = blockIdx.x * 32, y0 = blockIdx.y * 32;
    int tx = threadIdx.x, ty = threadIdx.y;   // 32 x 8
    const float* E  = g_E  + (size_t)b * N_ * M_;
    float*       ET = g_ET + (size_t)b * N_ * M_;
    #pragma unroll
    for (int q = 0; q < 32; q += 8)
        tile[ty+q][tx] = E[(size_t)(y0+ty+q) * M_ + x0 + tx];
    __syncthreads();
    #pragma unroll
    for (int q = 0; q < 32; q += 8)
        ET[(size_t)(x0+ty+q) * N_ + y0 + tx] = tile[tx][ty+q];
}

// ---------------- Sinkhorn U step: S_i = sum_j bexp_j * E_ij ----------------
__global__ void row_update_kernel() {
    if (g_done) return;
    int r = blockIdx.x;          // b*1024 + i
    int b = r >> 10;
    int t = threadIdx.x;         // 128
    const float4* erow = (const float4*)(g_E + (size_t)r * M_);
    const float4* bx   = (const float4*)(g_bexp + b * M_);
    float4 e0 = erow[t], e1 = erow[t + 128];
    float4 w0 = bx[t],   w1 = bx[t + 128];
    float s = e0.x*w0.x + e0.y*w0.y + e0.z*w0.z + e0.w*w0.w
            + e1.x*w1.x + e1.y*w1.y + e1.z*w1.z + e1.w*w1.w;
    #pragma unroll
    for (int o = 16; o; o >>= 1) s += __shfl_down_sync(0xffffffffu, s, o);
    __shared__ float ws[4];
    if ((t & 31) == 0) ws[t >> 5] = s;
    __syncthreads();
    if (t == 0) {
        float S = ws[0] + ws[1] + ws[2] + ws[3];
        float u_new = EPS_F * (LOG_MU - __logf(S));
        g_errbuf[r] = fabsf(u_new - g_u[r]);
        g_u[r]   = u_new;
        g_aexp[r] = MU_VAL / S;   // exp(u_new/eps), computed exactly
    }
}

// ---------------- Sinkhorn V step: T_j = sum_i aexp_i * E_ij ----------------
__global__ void col_update_kernel(const float* __restrict__ nu) {
    if (g_done) return;
    int c = blockIdx.x;          // b*1024 + j
    int b = c >> 10;
    int t = threadIdx.x;
    const float4* erow = (const float4*)(g_ET + (size_t)c * N_);
    const float4* ax   = (const float4*)(g_aexp + b * N_);
    float4 e0 = erow[t], e1 = erow[t + 128];
    float4 w0 = ax[t],   w1 = ax[t + 128];
    float s = e0.x*w0.x + e0.y*w0.y + e0.z*w0.z + e0.w*w0.w
            + e1.x*w1.x + e1.y*w1.y + e1.z*w1.z + e1.w*w1.w;
    #pragma unroll
    for (int o = 16; o; o >>= 1) s += __shfl_down_sync(0xffffffffu, s, o);
    __shared__ float ws[4];
    if ((t & 31) == 0) ws[t >> 5] = s;
    __syncthreads();
    if (t == 0) {
        float T = ws[0] + ws[1] + ws[2] + ws[3];
        g_bexp[c] = (nu[c] + 1e-8f) / T;   // exp(v_new/eps)
    }
}

// ---------------- convergence check (deterministic tree reduce) -------------
__global__ void check_kernel() {
    __shared__ float sm[1024];
    int t = threadIdx.x;
    float s = g_errbuf[t] + g_errbuf[t+1024] + g_errbuf[t+2048] + g_errbuf[t+3072];
    sm[t] = s;
    __syncthreads();
    for (int o = 512; o; o >>= 1) { if (t < o) sm[t] += sm[t + o]; __syncthreads(); }
    if (t == 0) {
        if (!g_done && (sm[0] * 0.25f) < THRESH_F) g_done = 1;
    }
}

// ---------------- final cost: sum_ij aexp_i E_ij bexp_j * C_ij --------------
__global__ void cost_row_kernel() {
    int r = blockIdx.x;
    int b = r >> 10;
    int t = threadIdx.x;
    const float4* erow = (const float4*)(g_E + (size_t)r * M_);
    const float4* bx   = (const float4*)(g_bexp + b * M_);
    float s = 0.0f;
    #pragma unroll
    for (int q = 0; q < 2; q++) {
        float4 e = erow[t + q*128];
        float4 w = bx[t + q*128];
        // C = -eps * log(E)
        s += e.x * w.x * (-EPS_F * __logf(e.x));
        s += e.y * w.y * (-EPS_F * __logf(e.y));
        s += e.z * w.z * (-EPS_F * __logf(e.z));
        s += e.w * w.w * (-EPS_F * __logf(e.w));
    }
    #pragma unroll
    for (int o = 16; o; o >>= 1) s += __shfl_down_sync(0xffffffffu, s, o);
    __shared__ float ws[4];
    if ((t & 31) == 0) ws[t >> 5] = s;
    __syncthreads();
    if (t == 0) g_rowsum[r] = g_aexp[r] * (ws[0] + ws[1] + ws[2] + ws[3]);
}

__global__ void cost_reduce_kernel(float* __restrict__ out) {
    int b = blockIdx.x;          // 0..3
    int t = threadIdx.x;         // 256
    __shared__ float sm[256];
    float s = 0.0f;
    #pragma unroll
    for (int q = 0; q < 4; q++) s += g_rowsum[b*1024 + t + q*256];
    sm[t] = s;
    __syncthreads();
    for (int o = 128; o; o >>= 1) { if (t < o) sm[t] += sm[t + o]; __syncthreads(); }
    if (t == 0) out[b] = sm[0];
}

// ---------------- launch ----------------
extern "C" void kernel_launch(void* const* d_in, const int* in_sizes, int n_in,
                              void* d_out, int out_size) {
    const float* x  = (const float*)d_in[0];
    const float* y  = (const float*)d_in[1];
    const float* nu = (const float*)d_in[2];
    float* out = (float*)d_out;

    norm_x_kernel<<<B_*N_, 128>>>(x);
    norm_y_kernel<<<B_*M_, 128>>>(y);
    init_kernel<<<16, 256>>>();

    dim3 gg(M_/128, N_/128, B_);
    gemm_exp_kernel<<<gg, 256>>>(x, y);
    transpose_kernel<<<dim3(M_/32, N_/32, B_), dim3(32, 8)>>>();

    for (int it = 0; it < 20; it++) {
        row_update_kernel<<<B_*N_, 128>>>();
        col_update_kernel<<<B_*M_, 128>>>(nu);
        check_kernel<<<1, 1024>>>();
    }

    cost_row_kernel<<<B_*N_, 128>>>();
    cost_reduce_kernel<<<B_, 256>>>(out);
}

// round 6
// speedup vs baseline: 1.4943x; 1.4943x over previous
#include <cuda_runtime.h>
#include <cuda_bf16.h>
#include <cstdint>
#include <math.h>

#define B_ 4
#define N_ 1024
#define M_ 1024
#define D_ 512
#define EPS_F 0.1f
#define INV_EPS 10.0f
#define THRESH_F 0.1f
#define LOG_MU -6.9314616f
#define MU_VAL (1.0f/1024.0f + 1e-8f)
#define NITER 20
#define GRID_P 148

// ---------------- scratch (no runtime allocation allowed) ----------------
__device__ float g_E [B_*N_*M_];    // fp32 exp(-C/eps), row-major
__device__ float g_ET[B_*N_*M_];    // fp32 transpose
__device__ __nv_bfloat16 g_xh[B_*N_*D_], g_xl[B_*N_*D_];
__device__ __nv_bfloat16 g_yh[B_*M_*D_], g_yl[B_*M_*D_];
__device__ float g_nx[B_*N_], g_ny[B_*M_];
__device__ float g_u[B_*N_], g_aexp[B_*N_], g_bexp[B_*M_];
__device__ float g_errbuf[B_*N_], g_rowsum[B_*N_];
__device__ int g_cnt;
__device__ volatile int g_gen;

// ---------------- helpers ----------------
__device__ __forceinline__ uint32_t smem_u32(const void* p) {
    uint32_t a;
    asm("{ .reg .u64 t; cvta.to.shared.u64 t, %1; cvt.u32.u64 %0, t; }"
        : "=r"(a) : "l"(p));
    return a;
}

__device__ __forceinline__ void ldsm_x4(uint32_t& r0, uint32_t& r1,
                                        uint32_t& r2, uint32_t& r3, uint32_t addr) {
    asm volatile("ldmatrix.sync.aligned.m8n8.x4.shared.b16 {%0,%1,%2,%3}, [%4];"
        : "=r"(r0), "=r"(r1), "=r"(r2), "=r"(r3) : "r"(addr));
}

__device__ __forceinline__ void mma16816(float* d, const uint32_t* a, const uint32_t* b) {
    asm volatile("mma.sync.aligned.m16n8k16.row.col.f32.bf16.bf16.f32 "
        "{%0,%1,%2,%3}, {%4,%5,%6,%7}, {%8,%9}, {%0,%1,%2,%3};"
        : "+f"(d[0]), "+f"(d[1]), "+f"(d[2]), "+f"(d[3])
        : "r"(a[0]), "r"(a[1]), "r"(a[2]), "r"(a[3]), "r"(b[0]), "r"(b[1]));
}

#define CP_ASYNC16(dst, src) \
    asm volatile("cp.async.cg.shared.global [%0], [%1], 16;" \
                 :: "r"(dst), "l"(src) : "memory")
#define CP_COMMIT() asm volatile("cp.async.commit_group;" ::: "memory")
#define CP_WAIT1()  asm volatile("cp.async.wait_group 1;" ::: "memory")
#define CP_WAIT0()  asm volatile("cp.async.wait_group 0;" ::: "memory")

// ---------------- norms + bf16 hi/lo split (fused) ----------------
// NOTE: device globals are referenced DIRECTLY in device code (host code must
// never pass __device__ symbols as kernel args — host shadow address != device
// address; on GB300 ATS that silently writes host RAM).
__device__ __forceinline__ void normsplit_body(const float* __restrict__ v,
                                               float* nrm,
                                               __nv_bfloat16* vh,
                                               __nv_bfloat16* vl) {
    int row = blockIdx.x;
    int t = threadIdx.x;                       // 128 threads, 4 floats each
    const float4* p = (const float4*)(v + (size_t)row * D_);
    float4 a = p[t];
    float s = a.x*a.x + a.y*a.y + a.z*a.z + a.w*a.w;

    __nv_bfloat16 h0 = __float2bfloat16(a.x), h1 = __float2bfloat16(a.y);
    __nv_bfloat16 h2 = __float2bfloat16(a.z), h3 = __float2bfloat16(a.w);
    __nv_bfloat16 l0 = __float2bfloat16(a.x - __bfloat162float(h0));
    __nv_bfloat16 l1 = __float2bfloat16(a.y - __bfloat162float(h1));
    __nv_bfloat16 l2 = __float2bfloat16(a.z - __bfloat162float(h2));
    __nv_bfloat16 l3 = __float2bfloat16(a.w - __bfloat162float(h3));
    size_t base = (size_t)row * D_ + t * 4;
    ((__nv_bfloat162*)(vh + base))[0] = __halves2bfloat162(h0, h1);
    ((__nv_bfloat162*)(vh + base))[1] = __halves2bfloat162(h2, h3);
    ((__nv_bfloat162*)(vl + base))[0] = __halves2bfloat162(l0, l1);
    ((__nv_bfloat162*)(vl + base))[1] = __halves2bfloat162(l2, l3);

    #pragma unroll
    for (int o = 16; o; o >>= 1) s += __shfl_down_sync(0xffffffffu, s, o);
    __shared__ float ws[4];
    if ((t & 31) == 0) ws[t >> 5] = s;
    __syncthreads();
    if (t == 0) nrm[row] = sqrtf(ws[0] + ws[1] + ws[2] + ws[3]);
}

__global__ void normsplit_x_kernel(const float* __restrict__ v) {
    normsplit_body(v, g_nx, g_xh, g_xl);
}
__global__ void normsplit_y_kernel(const float* __restrict__ v) {
    normsplit_body(v, g_ny, g_yh, g_yl);
}

// ---------------- mma.sync bf16-split GEMM + exp epilogue ----------------
// CTA tile 128x128, K-chunks of 64, 2-stage cp.async pipeline.
#define GS_STAGE 65536
#define GEMM_SMEM (2 * GS_STAGE)

__global__ __launch_bounds__(256, 1)
void gemm_mma_kernel() {
    extern __shared__ char smem[];
    const int tid = threadIdx.x;
    const int wid = tid >> 5, lane = tid & 31;
    const int b = blockIdx.z, i0 = blockIdx.y * 128, j0 = blockIdx.x * 128;
    const int wm = (wid & 3) * 32;      // warp row offset in tile
    const int wn = (wid >> 2) * 64;     // warp col offset in tile
    uint32_t sb = smem_u32(smem);

    const __nv_bfloat16* Axh = g_xh + ((size_t)b * N_ + i0) * D_;
    const __nv_bfloat16* Axl = g_xl + ((size_t)b * N_ + i0) * D_;
    const __nv_bfloat16* Byh = g_yh + ((size_t)b * M_ + j0) * D_;
    const __nv_bfloat16* Byl = g_yl + ((size_t)b * M_ + j0) * D_;
    const __nv_bfloat16* srcs[4] = {Axh, Axl, Byh, Byl};

    auto stage_load = [&](int c, int s) {
        #pragma unroll
        for (int tI = 0; tI < 4; tI++) {
            uint32_t tb = sb + s * GS_STAGE + tI * 16384;
            const __nv_bfloat16* src = srcs[tI];
            #pragma unroll
            for (int q = 0; q < 4; q++) {
                int idx = tid * 4 + q;            // 1024 chunks of 16B
                int row = idx >> 3, cc = idx & 7;
                uint32_t dst = tb + row * 128 + ((cc ^ (row & 7)) << 4);
                const __nv_bfloat16* g = src + (size_t)row * D_ + c * 64 + cc * 8;
                CP_ASYNC16(dst, (const void*)__cvta_generic_to_global(g));
            }
        }
    };

    float acc[2][8][4];
    #pragma unroll
    for (int mt = 0; mt < 2; mt++)
        #pragma unroll
        for (int nf = 0; nf < 8; nf++)
            #pragma unroll
            for (int q = 0; q < 4; q++) acc[mt][nf][q] = 0.f;

    stage_load(0, 0);
    CP_COMMIT();

    for (int c = 0; c < 8; c++) {
        if (c < 7) { stage_load(c + 1, (c + 1) & 1); CP_COMMIT(); CP_WAIT1(); }
        else       { CP_WAIT0(); }
        __syncthreads();

        uint32_t base = sb + (c & 1) * GS_STAGE;
        #pragma unroll
        for (int kk = 0; kk < 4; kk++) {
            uint32_t ah[2][4], al[2][4], bh[8][2], bl[8][2];
            #pragma unroll
            for (int mt = 0; mt < 2; mt++) {
                int row = wm + mt * 16 + ((lane >> 3) & 1) * 8 + (lane & 7);
                int seg = kk * 2 + (lane >> 4);
                uint32_t ad = base + row * 128 + ((seg ^ (row & 7)) << 4);
                ldsm_x4(ah[mt][0], ah[mt][1], ah[mt][2], ah[mt][3], ad);
                ldsm_x4(al[mt][0], al[mt][1], al[mt][2], al[mt][3], ad + 16384);
            }
            #pragma unroll
            for (int np = 0; np < 4; np++) {
                int row = wn + np * 16 + (lane >> 4) * 8 + (lane & 7);
                int seg = kk * 2 + ((lane >> 3) & 1);
                uint32_t ad = base + 32768 + row * 128 + ((seg ^ (row & 7)) << 4);
                ldsm_x4(bh[np*2][0], bh[np*2][1], bh[np*2+1][0], bh[np*2+1][1], ad);
                ldsm_x4(bl[np*2][0], bl[np*2][1], bl[np*2+1][0], bl[np*2+1][1], ad + 16384);
            }
            #pragma unroll
            for (int mt = 0; mt < 2; mt++)
                #pragma unroll
                for (int nf = 0; nf < 8; nf++) {
                    mma16816(acc[mt][nf], ah[mt], bh[nf]);
                    mma16816(acc[mt][nf], ah[mt], bl[nf]);
                    mma16816(acc[mt][nf], al[mt], bh[nf]);
                }
        }
        __syncthreads();
    }

    // epilogue: E = exp(-(1 - dot/denom)/eps), fp32 store
    #pragma unroll
    for (int mt = 0; mt < 2; mt++) {
        int r0 = i0 + wm + mt * 16 + (lane >> 2);
        float nx0 = g_nx[b * N_ + r0];
        float nx1 = g_nx[b * N_ + r0 + 8];
        #pragma unroll
        for (int nf = 0; nf < 8; nf++) {
            int c0 = j0 + wn + nf * 8 + (lane & 3) * 2;
            float ny0 = g_ny[b * M_ + c0];
            float ny1 = g_ny[b * M_ + c0 + 1];
            const float* a = acc[mt][nf];
            float e00 = __expf(-INV_EPS * (1.f - a[0] / fmaxf(nx0 * ny0, 1e-8f)));
            float e01 = __expf(-INV_EPS * (1.f - a[1] / fmaxf(nx0 * ny1, 1e-8f)));
            float e10 = __expf(-INV_EPS * (1.f - a[2] / fmaxf(nx1 * ny0, 1e-8f)));
            float e11 = __expf(-INV_EPS * (1.f - a[3] / fmaxf(nx1 * ny1, 1e-8f)));
            size_t ro0 = ((size_t)b * N_ + r0) * M_ + c0;
            size_t ro1 = ((size_t)b * N_ + r0 + 8) * M_ + c0;
            *(float2*)(g_E + ro0) = make_float2(e00, e01);
            *(float2*)(g_E + ro1) = make_float2(e10, e11);
        }
    }
}

// ---------------- fp32 transpose ----------------
__global__ void transpose_kernel() {
    __shared__ float tile[32][33];
    int b = blockIdx.z;
    int x0 = blockIdx.x * 32, y0 = blockIdx.y * 32;
    int tx = threadIdx.x, ty = threadIdx.y;     // 32 x 8
    const float* E  = g_E  + (size_t)b * N_ * M_;
    float*       ET = g_ET + (size_t)b * N_ * M_;
    #pragma unroll
    for (int q = 0; q < 32; q += 8)
        tile[ty + q][tx] = E[(size_t)(y0 + ty + q) * M_ + x0 + tx];
    __syncthreads();
    #pragma unroll
    for (int q = 0; q < 32; q += 8)
        ET[(size_t)(x0 + ty + q) * N_ + y0 + tx] = tile[tx][ty + q];
}

// ---------------- persistent Sinkhorn kernel ----------------
__device__ __forceinline__ void grid_sync_dev() {
    __syncthreads();
    if (threadIdx.x == 0) {
        int gen = g_gen;
        __threadfence();
        int prev = atomicAdd(&g_cnt, 1);
        if (prev == GRID_P - 1) {
            g_cnt = 0;
            __threadfence();
            g_gen = gen + 1;
        } else {
            while (g_gen == gen) { }
            __threadfence();
        }
    }
    __syncthreads();
}

__device__ __forceinline__ float dot_f32_row(const float4* erow, const float4* w, int lane) {
    float s = 0.f;
    #pragma unroll
    for (int p = 0; p < 8; p++) {
        float4 e = erow[p * 32 + lane];
        float4 wv = w[p * 32 + lane];
        s += e.x * wv.x + e.y * wv.y + e.z * wv.z + e.w * wv.w;
    }
    #pragma unroll
    for (int o = 16; o; o >>= 1) s += __shfl_down_sync(0xffffffffu, s, o);
    return s;
}

__global__ __launch_bounds__(256)
void sinkhorn_kernel(const float* __restrict__ nu, float* __restrict__ out) {
    const int t = threadIdx.x, wid = t >> 5, lane = t & 31;
    const int wgid = blockIdx.x * 8 + wid;
    __shared__ float red[256];

    {   // init: v=0 -> bexp=1, u=0
        int gid = blockIdx.x * 256 + t;
        if (gid < B_ * M_) { g_bexp[gid] = 1.0f; g_u[gid] = 0.0f; }
    }
    grid_sync_dev();

    bool done = false;
    for (int it = 0; it < NITER; it++) {
        // ---- u update (uses done entering this iteration) ----
        if (!done) {
            for (int r = wgid; r < B_ * N_; r += GRID_P * 8) {
                int b = r >> 10;
                float s = dot_f32_row((const float4*)(g_E + (size_t)r * M_),
                                      (const float4*)(g_bexp + (b << 10)), lane);
                if (lane == 0) {
                    float u_new = EPS_F * (LOG_MU - __logf(s));
                    g_errbuf[r] = fabsf(u_new - g_u[r]);
                    g_u[r] = u_new;
                    g_aexp[r] = MU_VAL / s;
                }
            }
        }
        grid_sync_dev();   // publishes g_aexp AND g_errbuf

        // ---- err reduction (race-free zone; identical in every CTA) ----
        float es = 0.f;
        #pragma unroll
        for (int k = 0; k < 16; k++) es += g_errbuf[t + k * 256];
        red[t] = es;
        __syncthreads();
        for (int o = 128; o; o >>= 1) { if (t < o) red[t] += red[t + o]; __syncthreads(); }
        float errv = red[0];
        __syncthreads();

        // ---- v update (still uses done entering this iteration) ----
        if (!done) {
            for (int c = wgid; c < B_ * M_; c += GRID_P * 8) {
                int b = c >> 10;
                float s = dot_f32_row((const float4*)(g_ET + (size_t)c * N_),
                                      (const float4*)(g_aexp + (b << 10)), lane);
                if (lane == 0)
                    g_bexp[c] = (__ldg(&nu[c]) + 1e-8f) / s;
            }
        }
        grid_sync_dev();   // publishes g_bexp; fences errbuf from next writer

        done = done || (errv * 0.25f < THRESH_F);
    }

    // final cost: sum_ij aexp_i * E_ij * bexp_j * (-eps*log E_ij)
    for (int r = wgid; r < B_ * N_; r += GRID_P * 8) {
        int b = r >> 10;
        const float4* erow = (const float4*)(g_E + (size_t)r * M_);
        const float4* w = (const float4*)(g_bexp + (b << 10));
        float s = 0.f;
        #pragma unroll
        for (int p = 0; p < 8; p++) {
            float4 e = erow[p * 32 + lane];
            float4 wv = w[p * 32 + lane];
            s += e.x * wv.x * __logf(e.x) + e.y * wv.y * __logf(e.y)
               + e.z * wv.z * __logf(e.z) + e.w * wv.w * __logf(e.w);
        }
        #pragma unroll
        for (int o = 16; o; o >>= 1) s += __shfl_down_sync(0xffffffffu, s, o);
        if (lane == 0) g_rowsum[r] = g_aexp[r] * s * (-EPS_F);
    }
    grid_sync_dev();
    if (blockIdx.x < B_) {
        int b = blockIdx.x;
        float s = 0.f;
        #pragma unroll
        for (int k = 0; k < 4; k++) s += g_rowsum[(b << 10) + t + k * 256];
        red[t] = s;
        __syncthreads();
        for (int o = 128; o; o >>= 1) { if (t < o) red[t] += red[t + o]; __syncthreads(); }
        if (t == 0) out[b] = red[0];
    }
}

// ---------------- launch ----------------
extern "C" void kernel_launch(void* const* d_in, const int* in_sizes, int n_in,
                              void* d_out, int out_size) {
    const float* x  = (const float*)d_in[0];
    const float* y  = (const float*)d_in[1];
    const float* nu = (const float*)d_in[2];
    float* out = (float*)d_out;

    cudaFuncSetAttribute(gemm_mma_kernel,
                         cudaFuncAttributeMaxDynamicSharedMemorySize, GEMM_SMEM);

    normsplit_x_kernel<<<B_ * N_, 128>>>(x);
    normsplit_y_kernel<<<B_ * M_, 128>>>(y);

    gemm_mma_kernel<<<dim3(8, 8, 4), 256, GEMM_SMEM>>>();
    transpose_kernel<<<dim3(32, 32, 4), dim3(32, 8)>>>();

    sinkhorn_kernel<<<GRID_P, 256>>>(nu, out);
}

// round 7
// speedup vs baseline: 2.5352x; 1.6966x over previous
#include <cuda_runtime.h>
#include <cuda_bf16.h>
#include <cstdint>
#include <math.h>

#define B_ 4
#define N_ 1024
#define M_ 1024
#define D_ 512
#define EPS_F 0.1f
#define INV_EPS 10.0f
#define THRESH_F 0.1f
#define LOG_MU -6.9314616f
#define MU_VAL (1.0f/1024.0f + 1e-8f)
#define NITER 20
#define GRID_P 148

// ---------------- scratch (no runtime allocation allowed) ----------------
__device__ float g_E [B_*N_*M_];    // fp32 exp(-C/eps), row-major
__device__ float g_ET[B_*N_*M_];    // fp32 transpose
__device__ float g_F [B_*N_*M_];    // fp32 E*C  (for final cost, no logf)
__device__ __nv_bfloat16 g_xh[B_*N_*D_], g_xl[B_*N_*D_];
__device__ __nv_bfloat16 g_yh[B_*M_*D_], g_yl[B_*M_*D_];
__device__ float g_nx[B_*N_], g_ny[B_*M_];
__device__ float g_u[B_*N_], g_aexp[B_*N_], g_bexp[B_*M_];
__device__ float g_errbuf[B_*N_], g_rowsum[B_*N_];
__device__ int g_cnt;
__device__ volatile int g_gen;

// ---------------- helpers ----------------
__device__ __forceinline__ uint32_t smem_u32(const void* p) {
    uint32_t a;
    asm("{ .reg .u64 t; cvta.to.shared.u64 t, %1; cvt.u32.u64 %0, t; }"
        : "=r"(a) : "l"(p));
    return a;
}

__device__ __forceinline__ void ldsm_x4(uint32_t& r0, uint32_t& r1,
                                        uint32_t& r2, uint32_t& r3, uint32_t addr) {
    asm volatile("ldmatrix.sync.aligned.m8n8.x4.shared.b16 {%0,%1,%2,%3}, [%4];"
        : "=r"(r0), "=r"(r1), "=r"(r2), "=r"(r3) : "r"(addr));
}

__device__ __forceinline__ void mma16816(float* d, const uint32_t* a, const uint32_t* b) {
    asm volatile("mma.sync.aligned.m16n8k16.row.col.f32.bf16.bf16.f32 "
        "{%0,%1,%2,%3}, {%4,%5,%6,%7}, {%8,%9}, {%0,%1,%2,%3};"
        : "+f"(d[0]), "+f"(d[1]), "+f"(d[2]), "+f"(d[3])
        : "r"(a[0]), "r"(a[1]), "r"(a[2]), "r"(a[3]), "r"(b[0]), "r"(b[1]));
}

#define CP_ASYNC16(dst, src) \
    asm volatile("cp.async.cg.shared.global [%0], [%1], 16;" \
                 :: "r"(dst), "l"(src) : "memory")
#define CP_COMMIT() asm volatile("cp.async.commit_group;" ::: "memory")
#define CP_WAIT1()  asm volatile("cp.async.wait_group 1;" ::: "memory")
#define CP_WAIT0()  asm volatile("cp.async.wait_group 0;" ::: "memory")

// ---------------- norms + bf16 hi/lo split (fused) ----------------
// Device globals referenced directly in device code only.
__device__ __forceinline__ void normsplit_body(const float* __restrict__ v,
                                               float* nrm,
                                               __nv_bfloat16* vh,
                                               __nv_bfloat16* vl) {
    int row = blockIdx.x;
    int t = threadIdx.x;                       // 128 threads, 4 floats each
    const float4* p = (const float4*)(v + (size_t)row * D_);
    float4 a = p[t];
    float s = a.x*a.x + a.y*a.y + a.z*a.z + a.w*a.w;

    __nv_bfloat16 h0 = __float2bfloat16(a.x), h1 = __float2bfloat16(a.y);
    __nv_bfloat16 h2 = __float2bfloat16(a.z), h3 = __float2bfloat16(a.w);
    __nv_bfloat16 l0 = __float2bfloat16(a.x - __bfloat162float(h0));
    __nv_bfloat16 l1 = __float2bfloat16(a.y - __bfloat162float(h1));
    __nv_bfloat16 l2 = __float2bfloat16(a.z - __bfloat162float(h2));
    __nv_bfloat16 l3 = __float2bfloat16(a.w - __bfloat162float(h3));
    size_t base = (size_t)row * D_ + t * 4;
    ((__nv_bfloat162*)(vh + base))[0] = __halves2bfloat162(h0, h1);
    ((__nv_bfloat162*)(vh + base))[1] = __halves2bfloat162(h2, h3);
    ((__nv_bfloat162*)(vl + base))[0] = __halves2bfloat162(l0, l1);
    ((__nv_bfloat162*)(vl + base))[1] = __halves2bfloat162(l2, l3);

    #pragma unroll
    for (int o = 16; o; o >>= 1) s += __shfl_down_sync(0xffffffffu, s, o);
    __shared__ float ws[4];
    if ((t & 31) == 0) ws[t >> 5] = s;
    __syncthreads();
    if (t == 0) nrm[row] = sqrtf(ws[0] + ws[1] + ws[2] + ws[3]);
}

__global__ void normsplit_x_kernel(const float* __restrict__ v) {
    normsplit_body(v, g_nx, g_xh, g_xl);
}
__global__ void normsplit_y_kernel(const float* __restrict__ v) {
    normsplit_body(v, g_ny, g_yh, g_yl);
}

// ---------------- mma.sync bf16-split GEMM + exp epilogue + fused transpose --
#define GS_STAGE 65536
#define GEMM_SMEM (2 * GS_STAGE)

__global__ __launch_bounds__(256, 1)
void gemm_mma_kernel() {
    extern __shared__ char smem[];
    const int tid = threadIdx.x;
    const int wid = tid >> 5, lane = tid & 31;
    const int b = blockIdx.z, i0 = blockIdx.y * 128, j0 = blockIdx.x * 128;
    const int wm = (wid & 3) * 32;      // warp row offset in tile
    const int wn = (wid >> 2) * 64;     // warp col offset in tile
    uint32_t sb = smem_u32(smem);

    const __nv_bfloat16* Axh = g_xh + ((size_t)b * N_ + i0) * D_;
    const __nv_bfloat16* Axl = g_xl + ((size_t)b * N_ + i0) * D_;
    const __nv_bfloat16* Byh = g_yh + ((size_t)b * M_ + j0) * D_;
    const __nv_bfloat16* Byl = g_yl + ((size_t)b * M_ + j0) * D_;
    const __nv_bfloat16* srcs[4] = {Axh, Axl, Byh, Byl};

    auto stage_load = [&](int c, int s) {
        #pragma unroll
        for (int tI = 0; tI < 4; tI++) {
            uint32_t tb = sb + s * GS_STAGE + tI * 16384;
            const __nv_bfloat16* src = srcs[tI];
            #pragma unroll
            for (int q = 0; q < 4; q++) {
                int idx = tid * 4 + q;            // 1024 chunks of 16B
                int row = idx >> 3, cc = idx & 7;
                uint32_t dst = tb + row * 128 + ((cc ^ (row & 7)) << 4);
                const __nv_bfloat16* g = src + (size_t)row * D_ + c * 64 + cc * 8;
                CP_ASYNC16(dst, (const void*)__cvta_generic_to_global(g));
            }
        }
    };

    float acc[2][8][4];
    #pragma unroll
    for (int mt = 0; mt < 2; mt++)
        #pragma unroll
        for (int nf = 0; nf < 8; nf++)
            #pragma unroll
            for (int q = 0; q < 4; q++) acc[mt][nf][q] = 0.f;

    stage_load(0, 0);
    CP_COMMIT();

    for (int c = 0; c < 8; c++) {
        if (c < 7) { stage_load(c + 1, (c + 1) & 1); CP_COMMIT(); CP_WAIT1(); }
        else       { CP_WAIT0(); }
        __syncthreads();

        uint32_t base = sb + (c & 1) * GS_STAGE;
        #pragma unroll
        for (int kk = 0; kk < 4; kk++) {
            uint32_t ah[2][4], al[2][4], bh[8][2], bl[8][2];
            #pragma unroll
            for (int mt = 0; mt < 2; mt++) {
                int row = wm + mt * 16 + ((lane >> 3) & 1) * 8 + (lane & 7);
                int seg = kk * 2 + (lane >> 4);
                uint32_t ad = base + row * 128 + ((seg ^ (row & 7)) << 4);
                ldsm_x4(ah[mt][0], ah[mt][1], ah[mt][2], ah[mt][3], ad);
                ldsm_x4(al[mt][0], al[mt][1], al[mt][2], al[mt][3], ad + 16384);
            }
            #pragma unroll
            for (int np = 0; np < 4; np++) {
                int row = wn + np * 16 + (lane >> 4) * 8 + (lane & 7);
                int seg = kk * 2 + ((lane >> 3) & 1);
                uint32_t ad = base + 32768 + row * 128 + ((seg ^ (row & 7)) << 4);
                ldsm_x4(bh[np*2][0], bh[np*2][1], bh[np*2+1][0], bh[np*2+1][1], ad);
                ldsm_x4(bl[np*2][0], bl[np*2][1], bl[np*2+1][0], bl[np*2+1][1], ad + 16384);
            }
            #pragma unroll
            for (int mt = 0; mt < 2; mt++)
                #pragma unroll
                for (int nf = 0; nf < 8; nf++) {
                    mma16816(acc[mt][nf], ah[mt], bh[nf]);
                    mma16816(acc[mt][nf], ah[mt], bl[nf]);
                    mma16816(acc[mt][nf], al[mt], bh[nf]);
                }
        }
        __syncthreads();
    }

    // epilogue: E = exp(-C/eps), F = E*C; stage E transposed in smem for ET.
    float* st = (float*)smem;                 // 128 x 132 floats = 67584 B
    #pragma unroll
    for (int mt = 0; mt < 2; mt++) {
        int lr0 = wm + mt * 16 + (lane >> 2);      // local row
        int r0 = i0 + lr0;
        float nx0 = g_nx[b * N_ + r0];
        float nx1 = g_nx[b * N_ + r0 + 8];
        #pragma unroll
        for (int nf = 0; nf < 8; nf++) {
            int lc0 = wn + nf * 8 + (lane & 3) * 2;
            int c0 = j0 + lc0;
            float ny0 = g_ny[b * M_ + c0];
            float ny1 = g_ny[b * M_ + c0 + 1];
            const float* a = acc[mt][nf];
            float C00 = 1.f - a[0] / fmaxf(nx0 * ny0, 1e-8f);
            float C01 = 1.f - a[1] / fmaxf(nx0 * ny1, 1e-8f);
            float C10 = 1.f - a[2] / fmaxf(nx1 * ny0, 1e-8f);
            float C11 = 1.f - a[3] / fmaxf(nx1 * ny1, 1e-8f);
            float e00 = __expf(-INV_EPS * C00);
            float e01 = __expf(-INV_EPS * C01);
            float e10 = __expf(-INV_EPS * C10);
            float e11 = __expf(-INV_EPS * C11);
            size_t ro0 = ((size_t)b * N_ + r0) * M_ + c0;
            size_t ro1 = ((size_t)b * N_ + r0 + 8) * M_ + c0;
            *(float2*)(g_E + ro0) = make_float2(e00, e01);
            *(float2*)(g_E + ro1) = make_float2(e10, e11);
            *(float2*)(g_F + ro0) = make_float2(e00 * C00, e01 * C01);
            *(float2*)(g_F + ro1) = make_float2(e10 * C10, e11 * C11);
            st[lc0 * 132 + lr0]           = e00;
            st[(lc0 + 1) * 132 + lr0]     = e01;
            st[lc0 * 132 + lr0 + 8]       = e10;
            st[(lc0 + 1) * 132 + lr0 + 8] = e11;
        }
    }
    __syncthreads();
    // ET tile: rows = global cols j0..j0+127, each 128 floats at i0
    {
        int jj = tid >> 1;                  // 0..127
        int half = (tid & 1) * 64;
        float* dst = g_ET + ((size_t)b * M_ + j0 + jj) * N_ + i0 + half;
        const float* srcrow = st + jj * 132 + half;
        #pragma unroll
        for (int k = 0; k < 64; k += 4)
            *(float4*)(dst + k) = *(const float4*)(srcrow + k);
    }
}

// ---------------- persistent Sinkhorn kernel ----------------
__device__ __forceinline__ void grid_sync_dev() {
    __syncthreads();
    if (threadIdx.x == 0) {
        int gen = g_gen;
        __threadfence();
        int prev = atomicAdd(&g_cnt, 1);
        if (prev == GRID_P - 1) {
            g_cnt = 0;
            __threadfence();
            g_gen = gen + 1;
        } else {
            while (g_gen == gen) { }
            __threadfence();
        }
    }
    __syncthreads();
}

__device__ __forceinline__ float dot_f32_row(const float4* erow, const float4* w, int lane) {
    float s = 0.f;
    #pragma unroll
    for (int p = 0; p < 8; p++) {
        float4 e = erow[p * 32 + lane];
        float4 wv = w[p * 32 + lane];
        s += e.x * wv.x + e.y * wv.y + e.z * wv.z + e.w * wv.w;
    }
    #pragma unroll
    for (int o = 16; o; o >>= 1) s += __shfl_down_sync(0xffffffffu, s, o);
    return s;
}

__global__ __launch_bounds__(256)
void sinkhorn_kernel(const float* __restrict__ nu, float* __restrict__ out) {
    const int t = threadIdx.x, wid = t >> 5, lane = t & 31;
    const int wgid = blockIdx.x * 8 + wid;
    __shared__ float red[256];

    {   // init: v=0 -> bexp=1, u=0
        int gid = blockIdx.x * 256 + t;
        if (gid < B_ * M_) { g_bexp[gid] = 1.0f; g_u[gid] = 0.0f; }
    }
    grid_sync_dev();

    for (int it = 0; it < NITER; it++) {
        // ---- u update ----
        for (int r = wgid; r < B_ * N_; r += GRID_P * 8) {
            int b = r >> 10;
            float s = dot_f32_row((const float4*)(g_E + (size_t)r * M_),
                                  (const float4*)(g_bexp + (b << 10)), lane);
            if (lane == 0) {
                float u_new = EPS_F * (LOG_MU - __logf(s));
                g_errbuf[r] = fabsf(u_new - g_u[r]);
                g_u[r] = u_new;
                g_aexp[r] = MU_VAL / s;
            }
        }
        grid_sync_dev();   // publishes g_aexp AND g_errbuf

        // ---- err reduction (race-free window; identical in every CTA) ----
        float es = 0.f;
        #pragma unroll
        for (int k = 0; k < 16; k++) es += g_errbuf[t + k * 256];
        red[t] = es;
        __syncthreads();
        for (int o = 128; o; o >>= 1) { if (t < o) red[t] += red[t + o]; __syncthreads(); }
        float errv = red[0];
        __syncthreads();

        // ---- v update ----
        for (int c = wgid; c < B_ * M_; c += GRID_P * 8) {
            int b = c >> 10;
            float s = dot_f32_row((const float4*)(g_ET + (size_t)c * N_),
                                  (const float4*)(g_aexp + (b << 10)), lane);
            if (lane == 0)
                g_bexp[c] = (__ldg(&nu[c]) + 1e-8f) / s;
        }
        grid_sync_dev();   // publishes g_bexp; fences errbuf from next writer

        // done-freeze: all remaining reference iterations are exact no-ops
        if (errv * 0.25f < THRESH_F) break;   // identical errv in all CTAs
    }

    // final cost: sum_i aexp_i * (sum_j F_ij * bexp_j),  F = E*C (exact C)
    for (int r = wgid; r < B_ * N_; r += GRID_P * 8) {
        int b = r >> 10;
        float s = dot_f32_row((const float4*)(g_F + (size_t)r * M_),
                              (const float4*)(g_bexp + (b << 10)), lane);
        if (lane == 0) g_rowsum[r] = g_aexp[r] * s;
    }
    grid_sync_dev();
    if (blockIdx.x < B_) {
        int b = blockIdx.x;
        float s = 0.f;
        #pragma unroll
        for (int k = 0; k < 4; k++) s += g_rowsum[(b << 10) + t + k * 256];
        red[t] = s;
        __syncthreads();
        for (int o = 128; o; o >>= 1) { if (t < o) red[t] += red[t + o]; __syncthreads(); }
        if (t == 0) out[b] = red[0];
    }
}

// ---------------- launch ----------------
extern "C" void kernel_launch(void* const* d_in, const int* in_sizes, int n_in,
                              void* d_out, int out_size) {
    const float* x  = (const float*)d_in[0];
    const float* y  = (const float*)d_in[1];
    const float* nu = (const float*)d_in[2];
    float* out = (float*)d_out;

    cudaFuncSetAttribute(gemm_mma_kernel,
                         cudaFuncAttributeMaxDynamicSharedMemorySize, GEMM_SMEM);

    normsplit_x_kernel<<<B_ * N_, 128>>>(x);
    normsplit_y_kernel<<<B_ * M_, 128>>>(y);

    gemm_mma_kernel<<<dim3(8, 8, 4), 256, GEMM_SMEM>>>();

    sinkhorn_kernel<<<GRID_P, 256>>>(nu, out);
}

// round 8
// speedup vs baseline: 2.8797x; 1.1359x over previous
#include <cuda_runtime.h>
#include <cuda_bf16.h>
#include <cstdint>
#include <math.h>

#define B_ 4
#define N_ 1024
#define M_ 1024
#define D_ 512
#define EPS_F 0.1f
#define INV_EPS 10.0f
#define THRESH_F 0.1f
#define LOG_MU -6.9314616f
#define MU_VAL (1.0f/1024.0f + 1e-8f)
#define NITER 20
#define GRID_P 148
#define SINK_T 1024
#define SINK_W (GRID_P * (SINK_T / 32))

// ---------------- scratch (no runtime allocation allowed) ----------------
__device__ float g_E [B_*N_*M_];    // fp32 exp(-C/eps), row-major
__device__ float g_ET[B_*N_*M_];    // fp32 transpose
__device__ float g_F [B_*N_*M_];    // fp32 E*C  (for final cost, no logf)
__device__ __nv_bfloat16 g_xh[B_*N_*D_], g_xl[B_*N_*D_];
__device__ __nv_bfloat16 g_yh[B_*M_*D_], g_yl[B_*M_*D_];
__device__ float g_nx[B_*N_], g_ny[B_*M_];
__device__ float g_u[B_*N_], g_aexp[B_*N_], g_bexp[B_*M_];
__device__ float g_errbuf[B_*N_], g_rowsum[B_*N_];
__device__ int g_cnt;
__device__ volatile int g_gen;

// ---------------- helpers ----------------
__device__ __forceinline__ uint32_t smem_u32(const void* p) {
    uint32_t a;
    asm("{ .reg .u64 t; cvta.to.shared.u64 t, %1; cvt.u32.u64 %0, t; }"
        : "=r"(a) : "l"(p));
    return a;
}

__device__ __forceinline__ void ldsm_x4(uint32_t& r0, uint32_t& r1,
                                        uint32_t& r2, uint32_t& r3, uint32_t addr) {
    asm volatile("ldmatrix.sync.aligned.m8n8.x4.shared.b16 {%0,%1,%2,%3}, [%4];"
        : "=r"(r0), "=r"(r1), "=r"(r2), "=r"(r3) : "r"(addr));
}

__device__ __forceinline__ void mma16816(float* d, const uint32_t* a, const uint32_t* b) {
    asm volatile("mma.sync.aligned.m16n8k16.row.col.f32.bf16.bf16.f32 "
        "{%0,%1,%2,%3}, {%4,%5,%6,%7}, {%8,%9}, {%0,%1,%2,%3};"
        : "+f"(d[0]), "+f"(d[1]), "+f"(d[2]), "+f"(d[3])
        : "r"(a[0]), "r"(a[1]), "r"(a[2]), "r"(a[3]), "r"(b[0]), "r"(b[1]));
}

#define CP_ASYNC16(dst, src) \
    asm volatile("cp.async.cg.shared.global [%0], [%1], 16;" \
                 :: "r"(dst), "l"(src) : "memory")
#define CP_COMMIT() asm volatile("cp.async.commit_group;" ::: "memory")
#define CP_WAIT1()  asm volatile("cp.async.wait_group 1;" ::: "memory")
#define CP_WAIT0()  asm volatile("cp.async.wait_group 0;" ::: "memory")

// ---------------- norms + bf16 hi/lo split (fused) ----------------
__device__ __forceinline__ void normsplit_body(const float* __restrict__ v,
                                               float* nrm,
                                               __nv_bfloat16* vh,
                                               __nv_bfloat16* vl) {
    int row = blockIdx.x;
    int t = threadIdx.x;                       // 128 threads, 4 floats each
    const float4* p = (const float4*)(v + (size_t)row * D_);
    float4 a = p[t];
    float s = a.x*a.x + a.y*a.y + a.z*a.z + a.w*a.w;

    __nv_bfloat16 h0 = __float2bfloat16(a.x), h1 = __float2bfloat16(a.y);
    __nv_bfloat16 h2 = __float2bfloat16(a.z), h3 = __float2bfloat16(a.w);
    __nv_bfloat16 l0 = __float2bfloat16(a.x - __bfloat162float(h0));
    __nv_bfloat16 l1 = __float2bfloat16(a.y - __bfloat162float(h1));
    __nv_bfloat16 l2 = __float2bfloat16(a.z - __bfloat162float(h2));
    __nv_bfloat16 l3 = __float2bfloat16(a.w - __bfloat162float(h3));
    size_t base = (size_t)row * D_ + t * 4;
    ((__nv_bfloat162*)(vh + base))[0] = __halves2bfloat162(h0, h1);
    ((__nv_bfloat162*)(vh + base))[1] = __halves2bfloat162(h2, h3);
    ((__nv_bfloat162*)(vl + base))[0] = __halves2bfloat162(l0, l1);
    ((__nv_bfloat162*)(vl + base))[1] = __halves2bfloat162(l2, l3);

    #pragma unroll
    for (int o = 16; o; o >>= 1) s += __shfl_down_sync(0xffffffffu, s, o);
    __shared__ float ws[4];
    if ((t & 31) == 0) ws[t >> 5] = s;
    __syncthreads();
    if (t == 0) nrm[row] = sqrtf(ws[0] + ws[1] + ws[2] + ws[3]);
}

__global__ void normsplit_x_kernel(const float* __restrict__ v) {
    normsplit_body(v, g_nx, g_xh, g_xl);
}
__global__ void normsplit_y_kernel(const float* __restrict__ v) {
    normsplit_body(v, g_ny, g_yh, g_yl);
}

// ---------------- mma.sync bf16-split GEMM + exp epilogue + fused transpose --
#define GS_STAGE 65536
#define GEMM_SMEM (2 * GS_STAGE)

__global__ __launch_bounds__(256, 1)
void gemm_mma_kernel() {
    extern __shared__ char smem[];
    const int tid = threadIdx.x;
    const int wid = tid >> 5, lane = tid & 31;
    const int b = blockIdx.z, i0 = blockIdx.y * 128, j0 = blockIdx.x * 128;
    const int wm = (wid & 3) * 32;      // warp row offset in tile
    const int wn = (wid >> 2) * 64;     // warp col offset in tile
    uint32_t sb = smem_u32(smem);

    const __nv_bfloat16* Axh = g_xh + ((size_t)b * N_ + i0) * D_;
    const __nv_bfloat16* Axl = g_xl + ((size_t)b * N_ + i0) * D_;
    const __nv_bfloat16* Byh = g_yh + ((size_t)b * M_ + j0) * D_;
    const __nv_bfloat16* Byl = g_yl + ((size_t)b * M_ + j0) * D_;
    const __nv_bfloat16* srcs[4] = {Axh, Axl, Byh, Byl};

    auto stage_load = [&](int c, int s) {
        #pragma unroll
        for (int tI = 0; tI < 4; tI++) {
            uint32_t tb = sb + s * GS_STAGE + tI * 16384;
            const __nv_bfloat16* src = srcs[tI];
            #pragma unroll
            for (int q = 0; q < 4; q++) {
                int idx = tid * 4 + q;            // 1024 chunks of 16B
                int row = idx >> 3, cc = idx & 7;
                uint32_t dst = tb + row * 128 + ((cc ^ (row & 7)) << 4);
                const __nv_bfloat16* g = src + (size_t)row * D_ + c * 64 + cc * 8;
                CP_ASYNC16(dst, (const void*)__cvta_generic_to_global(g));
            }
        }
    };

    float acc[2][8][4];
    #pragma unroll
    for (int mt = 0; mt < 2; mt++)
        #pragma unroll
        for (int nf = 0; nf < 8; nf++)
            #pragma unroll
            for (int q = 0; q < 4; q++) acc[mt][nf][q] = 0.f;

    stage_load(0, 0);
    CP_COMMIT();

    for (int c = 0; c < 8; c++) {
        if (c < 7) { stage_load(c + 1, (c + 1) & 1); CP_COMMIT(); CP_WAIT1(); }
        else       { CP_WAIT0(); }
        __syncthreads();

        uint32_t base = sb + (c & 1) * GS_STAGE;
        #pragma unroll
        for (int kk = 0; kk < 4; kk++) {
            uint32_t ah[2][4], al[2][4], bh[8][2], bl[8][2];
            #pragma unroll
            for (int mt = 0; mt < 2; mt++) {
                int row = wm + mt * 16 + ((lane >> 3) & 1) * 8 + (lane & 7);
                int seg = kk * 2 + (lane >> 4);
                uint32_t ad = base + row * 128 + ((seg ^ (row & 7)) << 4);
                ldsm_x4(ah[mt][0], ah[mt][1], ah[mt][2], ah[mt][3], ad);
                ldsm_x4(al[mt][0], al[mt][1], al[mt][2], al[mt][3], ad + 16384);
            }
            #pragma unroll
            for (int np = 0; np < 4; np++) {
                int row = wn + np * 16 + (lane >> 4) * 8 + (lane & 7);
                int seg = kk * 2 + ((lane >> 3) & 1);
                uint32_t ad = base + 32768 + row * 128 + ((seg ^ (row & 7)) << 4);
                ldsm_x4(bh[np*2][0], bh[np*2][1], bh[np*2+1][0], bh[np*2+1][1], ad);
                ldsm_x4(bl[np*2][0], bl[np*2][1], bl[np*2+1][0], bl[np*2+1][1], ad + 16384);
            }
            #pragma unroll
            for (int mt = 0; mt < 2; mt++)
                #pragma unroll
                for (int nf = 0; nf < 8; nf++) {
                    mma16816(acc[mt][nf], ah[mt], bh[nf]);
                    mma16816(acc[mt][nf], ah[mt], bl[nf]);
                    mma16816(acc[mt][nf], al[mt], bh[nf]);
                }
        }
        __syncthreads();
    }

    // epilogue: E = exp(-C/eps), F = E*C; stage E transposed in smem for ET.
    float* st = (float*)smem;                 // 128 x 132 floats = 67584 B
    #pragma unroll
    for (int mt = 0; mt < 2; mt++) {
        int lr0 = wm + mt * 16 + (lane >> 2);      // local row
        int r0 = i0 + lr0;
        float nx0 = g_nx[b * N_ + r0];
        float nx1 = g_nx[b * N_ + r0 + 8];
        #pragma unroll
        for (int nf = 0; nf < 8; nf++) {
            int lc0 = wn + nf * 8 + (lane & 3) * 2;
            int c0 = j0 + lc0;
            float ny0 = g_ny[b * M_ + c0];
            float ny1 = g_ny[b * M_ + c0 + 1];
            const float* a = acc[mt][nf];
            float C00 = 1.f - a[0] / fmaxf(nx0 * ny0, 1e-8f);
            float C01 = 1.f - a[1] / fmaxf(nx0 * ny1, 1e-8f);
            float C10 = 1.f - a[2] / fmaxf(nx1 * ny0, 1e-8f);
            float C11 = 1.f - a[3] / fmaxf(nx1 * ny1, 1e-8f);
            float e00 = __expf(-INV_EPS * C00);
            float e01 = __expf(-INV_EPS * C01);
            float e10 = __expf(-INV_EPS * C10);
            float e11 = __expf(-INV_EPS * C11);
            size_t ro0 = ((size_t)b * N_ + r0) * M_ + c0;
            size_t ro1 = ((size_t)b * N_ + r0 + 8) * M_ + c0;
            *(float2*)(g_E + ro0) = make_float2(e00, e01);
            *(float2*)(g_E + ro1) = make_float2(e10, e11);
            *(float2*)(g_F + ro0) = make_float2(e00 * C00, e01 * C01);
            *(float2*)(g_F + ro1) = make_float2(e10 * C10, e11 * C11);
            st[lc0 * 132 + lr0]           = e00;
            st[(lc0 + 1) * 132 + lr0]     = e01;
            st[lc0 * 132 + lr0 + 8]       = e10;
            st[(lc0 + 1) * 132 + lr0 + 8] = e11;
        }
    }
    __syncthreads();
    // ET tile: rows = global cols j0..j0+127, each 128 floats at i0
    {
        int jj = tid >> 1;                  // 0..127
        int half = (tid & 1) * 64;
        float* dst = g_ET + ((size_t)b * M_ + j0 + jj) * N_ + i0 + half;
        const float* srcrow = st + jj * 132 + half;
        #pragma unroll
        for (int k = 0; k < 64; k += 4)
            *(float4*)(dst + k) = *(const float4*)(srcrow + k);
    }
}

// ---------------- persistent Sinkhorn kernel (1024 threads/CTA) ----------------
__device__ __forceinline__ void grid_sync_dev() {
    __syncthreads();
    if (threadIdx.x == 0) {
        int gen = g_gen;
        __threadfence();
        int prev = atomicAdd(&g_cnt, 1);
        if (prev == GRID_P - 1) {
            g_cnt = 0;
            __threadfence();
            g_gen = gen + 1;
        } else {
            while (g_gen == gen) { }
            __threadfence();
        }
    }
    __syncthreads();
}

__device__ __forceinline__ float dot_f32_row(const float4* erow, const float4* w, int lane) {
    float s = 0.f;
    #pragma unroll
    for (int p = 0; p < 8; p++) {
        float4 e = erow[p * 32 + lane];
        float4 wv = w[p * 32 + lane];
        s += e.x * wv.x + e.y * wv.y + e.z * wv.z + e.w * wv.w;
    }
    #pragma unroll
    for (int o = 16; o; o >>= 1) s += __shfl_down_sync(0xffffffffu, s, o);
    return s;
}

__global__ __launch_bounds__(SINK_T)
void sinkhorn_kernel(const float* __restrict__ nu, float* __restrict__ out) {
    const int t = threadIdx.x, wid = t >> 5, lane = t & 31;
    const int wgid = blockIdx.x * (SINK_T / 32) + wid;   // 0..SINK_W-1
    __shared__ float red[SINK_T];

    {   // init: v=0 -> bexp=1, u=0
        int gid = blockIdx.x * SINK_T + t;
        if (gid < B_ * M_) { g_bexp[gid] = 1.0f; g_u[gid] = 0.0f; }
    }
    grid_sync_dev();

    for (int it = 0; it < NITER; it++) {
        // ---- u update (~1 row per warp) ----
        for (int r = wgid; r < B_ * N_; r += SINK_W) {
            int b = r >> 10;
            float s = dot_f32_row((const float4*)(g_E + (size_t)r * M_),
                                  (const float4*)(g_bexp + (b << 10)), lane);
            if (lane == 0) {
                float u_new = EPS_F * (LOG_MU - __logf(s));
                g_errbuf[r] = fabsf(u_new - g_u[r]);
                g_u[r] = u_new;
                g_aexp[r] = MU_VAL / s;
            }
        }
        grid_sync_dev();   // publishes g_aexp AND g_errbuf

        // ---- err reduction (race-free window; identical in every CTA) ----
        float es = g_errbuf[t] + g_errbuf[t + 1024]
                 + g_errbuf[t + 2048] + g_errbuf[t + 3072];
        red[t] = es;
        __syncthreads();
        for (int o = SINK_T / 2; o; o >>= 1) {
            if (t < o) red[t] += red[t + o];
            __syncthreads();
        }
        float errv = red[0];
        __syncthreads();

        // ---- v update ----
        for (int c = wgid; c < B_ * M_; c += SINK_W) {
            int b = c >> 10;
            float s = dot_f32_row((const float4*)(g_ET + (size_t)c * N_),
                                  (const float4*)(g_aexp + (b << 10)), lane);
            if (lane == 0)
                g_bexp[c] = (__ldg(&nu[c]) + 1e-8f) / s;
        }
        grid_sync_dev();   // publishes g_bexp; fences errbuf from next writer

        // done-freeze: all remaining reference iterations are exact no-ops
        if (errv * 0.25f < THRESH_F) break;   // identical errv in all CTAs
    }

    // final cost: sum_i aexp_i * (sum_j F_ij * bexp_j),  F = E*C (exact C)
    for (int r = wgid; r < B_ * N_; r += SINK_W) {
        int b = r >> 10;
        float s = dot_f32_row((const float4*)(g_F + (size_t)r * M_),
                              (const float4*)(g_bexp + (b << 10)), lane);
        if (lane == 0) g_rowsum[r] = g_aexp[r] * s;
    }
    grid_sync_dev();
    if (blockIdx.x < B_) {
        int b = blockIdx.x;
        red[t] = g_rowsum[(b << 10) + t];
        __syncthreads();
        for (int o = 512; o; o >>= 1) {
            if (t < o) red[t] += red[t + o];
            __syncthreads();
        }
        if (t == 0) out[b] = red[0];
    }
}

// ---------------- launch ----------------
extern "C" void kernel_launch(void* const* d_in, const int* in_sizes, int n_in,
                              void* d_out, int out_size) {
    const float* x  = (const float*)d_in[0];
    const float* y  = (const float*)d_in[1];
    const float* nu = (const float*)d_in[2];
    float* out = (float*)d_out;

    cudaFuncSetAttribute(gemm_mma_kernel,
                         cudaFuncAttributeMaxDynamicSharedMemorySize, GEMM_SMEM);

    normsplit_x_kernel<<<B_ * N_, 128>>>(x);
    normsplit_y_kernel<<<B_ * M_, 128>>>(y);

    gemm_mma_kernel<<<dim3(8, 8, 4), 256, GEMM_SMEM>>>();

    sinkhorn_kernel<<<GRID_P, SINK_T>>>(nu, out);
}

// round 9
// speedup vs baseline: 3.3110x; 1.1498x over previous
#include <cuda_runtime.h>
#include <cuda_bf16.h>
#include <cstdint>
#include <math.h>

#define B_ 4
#define N_ 1024
#define M_ 1024
#define D_ 512
#define EPS_F 0.1f
#define INV_EPS 10.0f
#define THRESH_F 0.1f
#define LOG_MU -6.9314616f
#define MU_VAL (1.0f/1024.0f + 1e-8f)
#define NITER 20
#define GRID_P 148
#define SINK_T 1024
#define SINK_W (GRID_P * (SINK_T / 32))

// ---------------- scratch (no runtime allocation allowed) ----------------
__device__ float g_E [B_*N_*M_];    // fp32 exp(-C/eps), row-major
__device__ float g_ET[B_*N_*M_];    // fp32 transpose
__device__ float g_F [B_*N_*M_];    // fp32 E*C  (for final cost, no logf)
__device__ __nv_bfloat16 g_xh[B_*N_*D_], g_xl[B_*N_*D_];
__device__ __nv_bfloat16 g_yh[B_*M_*D_], g_yl[B_*M_*D_];
__device__ float g_nx[B_*N_], g_ny[B_*M_];
__device__ float g_u[B_*N_], g_aexp[B_*N_], g_bexp[B_*M_];
__device__ float g_errbuf[B_*N_], g_rowsum[B_*N_];
__device__ int g_cnt;
__device__ volatile int g_gen;

// ---------------- helpers ----------------
__device__ __forceinline__ uint32_t smem_u32(const void* p) {
    uint32_t a;
    asm("{ .reg .u64 t; cvta.to.shared.u64 t, %1; cvt.u32.u64 %0, t; }"
        : "=r"(a) : "l"(p));
    return a;
}

__device__ __forceinline__ void ldsm_x4(uint32_t& r0, uint32_t& r1,
                                        uint32_t& r2, uint32_t& r3, uint32_t addr) {
    asm volatile("ldmatrix.sync.aligned.m8n8.x4.shared.b16 {%0,%1,%2,%3}, [%4];"
        : "=r"(r0), "=r"(r1), "=r"(r2), "=r"(r3) : "r"(addr));
}

__device__ __forceinline__ void mma16816(float* d, const uint32_t* a, const uint32_t* b) {
    asm volatile("mma.sync.aligned.m16n8k16.row.col.f32.bf16.bf16.f32 "
        "{%0,%1,%2,%3}, {%4,%5,%6,%7}, {%8,%9}, {%0,%1,%2,%3};"
        : "+f"(d[0]), "+f"(d[1]), "+f"(d[2]), "+f"(d[3])
        : "r"(a[0]), "r"(a[1]), "r"(a[2]), "r"(a[3]), "r"(b[0]), "r"(b[1]));
}

#define CP_ASYNC16(dst, src) \
    asm volatile("cp.async.cg.shared.global [%0], [%1], 16;" \
                 :: "r"(dst), "l"(src) : "memory")
#define CP_COMMIT() asm volatile("cp.async.commit_group;" ::: "memory")
#define CP_WAIT1()  asm volatile("cp.async.wait_group 1;" ::: "memory")
#define CP_WAIT0()  asm volatile("cp.async.wait_group 0;" ::: "memory")

// ---------------- norms + bf16 hi/lo split (fused, single launch) ----------
__device__ __forceinline__ void normsplit_body(const float* __restrict__ v,
                                               int row, float* nrm,
                                               __nv_bfloat16* vh,
                                               __nv_bfloat16* vl) {
    int t = threadIdx.x;                       // 128 threads, 4 floats each
    const float4* p = (const float4*)(v + (size_t)row * D_);
    float4 a = p[t];
    float s = a.x*a.x + a.y*a.y + a.z*a.z + a.w*a.w;

    __nv_bfloat16 h0 = __float2bfloat16(a.x), h1 = __float2bfloat16(a.y);
    __nv_bfloat16 h2 = __float2bfloat16(a.z), h3 = __float2bfloat16(a.w);
    __nv_bfloat16 l0 = __float2bfloat16(a.x - __bfloat162float(h0));
    __nv_bfloat16 l1 = __float2bfloat16(a.y - __bfloat162float(h1));
    __nv_bfloat16 l2 = __float2bfloat16(a.z - __bfloat162float(h2));
    __nv_bfloat16 l3 = __float2bfloat16(a.w - __bfloat162float(h3));
    size_t base = (size_t)row * D_ + t * 4;
    ((__nv_bfloat162*)(vh + base))[0] = __halves2bfloat162(h0, h1);
    ((__nv_bfloat162*)(vh + base))[1] = __halves2bfloat162(h2, h3);
    ((__nv_bfloat162*)(vl + base))[0] = __halves2bfloat162(l0, l1);
    ((__nv_bfloat162*)(vl + base))[1] = __halves2bfloat162(l2, l3);

    #pragma unroll
    for (int o = 16; o; o >>= 1) s += __shfl_down_sync(0xffffffffu, s, o);
    __shared__ float ws[4];
    if ((t & 31) == 0) ws[t >> 5] = s;
    __syncthreads();
    if (t == 0) nrm[row] = sqrtf(ws[0] + ws[1] + ws[2] + ws[3]);
}

__global__ void normsplit_kernel(const float* __restrict__ x,
                                 const float* __restrict__ y) {
    int row = blockIdx.x;
    if (row < B_ * N_) normsplit_body(x, row, g_nx, g_xh, g_xl);
    else               normsplit_body(y, row - B_ * N_, g_ny, g_yh, g_yl);
}

// ---------------- mma.sync bf16-split GEMM, 128x64 tiles, 2 CTAs/SM --------
// stage layout: Ah@0 (16KB), Al@16384, Bh@32768 (8KB), Bl@40960; 48KB/stage.
#define GS_STAGE 49152
#define GEMM_SMEM (2 * GS_STAGE)   // 96KB -> 2 CTAs/SM

__global__ __launch_bounds__(256, 2)
void gemm_mma_kernel() {
    extern __shared__ char smem[];
    const int tid = threadIdx.x;
    const int wid = tid >> 5, lane = tid & 31;
    const int b = blockIdx.z, i0 = blockIdx.y * 128, j0 = blockIdx.x * 64;
    const int wm = (wid & 3) * 32;      // warp row offset (0..96)
    const int wn = (wid >> 2) * 32;     // warp col offset (0 or 32)
    uint32_t sb = smem_u32(smem);

    const __nv_bfloat16* Axh = g_xh + ((size_t)b * N_ + i0) * D_;
    const __nv_bfloat16* Axl = g_xl + ((size_t)b * N_ + i0) * D_;
    const __nv_bfloat16* Byh = g_yh + ((size_t)b * M_ + j0) * D_;
    const __nv_bfloat16* Byl = g_yl + ((size_t)b * M_ + j0) * D_;

    // A tiles: 128 rows x 8 16B-chunks = 1024 chunks; B tiles: 64 x 8 = 512.
    auto stage_load = [&](int c, int s) {
        uint32_t tb = sb + s * GS_STAGE;
        #pragma unroll
        for (int q = 0; q < 4; q++) {
            int idx = q * 256 + tid;
            int row = idx >> 3, cc = idx & 7;
            uint32_t off = row * 128 + ((cc ^ (row & 7)) << 4);
            const __nv_bfloat16* gh = Axh + (size_t)row * D_ + c * 64 + cc * 8;
            const __nv_bfloat16* gl = Axl + (size_t)row * D_ + c * 64 + cc * 8;
            CP_ASYNC16(tb + off,         (const void*)__cvta_generic_to_global(gh));
            CP_ASYNC16(tb + 16384 + off, (const void*)__cvta_generic_to_global(gl));
        }
        #pragma unroll
        for (int q = 0; q < 2; q++) {
            int idx = q * 256 + tid;
            int row = idx >> 3, cc = idx & 7;
            uint32_t off = row * 128 + ((cc ^ (row & 7)) << 4);
            const __nv_bfloat16* gh = Byh + (size_t)row * D_ + c * 64 + cc * 8;
            const __nv_bfloat16* gl = Byl + (size_t)row * D_ + c * 64 + cc * 8;
            CP_ASYNC16(tb + 32768 + off, (const void*)__cvta_generic_to_global(gh));
            CP_ASYNC16(tb + 40960 + off, (const void*)__cvta_generic_to_global(gl));
        }
    };

    float acc[2][4][4];
    #pragma unroll
    for (int mt = 0; mt < 2; mt++)
        #pragma unroll
        for (int nf = 0; nf < 4; nf++)
            #pragma unroll
            for (int q = 0; q < 4; q++) acc[mt][nf][q] = 0.f;

    stage_load(0, 0);
    CP_COMMIT();

    for (int c = 0; c < 8; c++) {
        if (c < 7) { stage_load(c + 1, (c + 1) & 1); CP_COMMIT(); CP_WAIT1(); }
        else       { CP_WAIT0(); }
        __syncthreads();

        uint32_t base = sb + (c & 1) * GS_STAGE;
        #pragma unroll
        for (int kk = 0; kk < 4; kk++) {
            uint32_t ah[2][4], al[2][4], bh[4][2], bl[4][2];
            #pragma unroll
            for (int mt = 0; mt < 2; mt++) {
                int row = wm + mt * 16 + ((lane >> 3) & 1) * 8 + (lane & 7);
                int seg = kk * 2 + (lane >> 4);
                uint32_t ad = base + row * 128 + ((seg ^ (row & 7)) << 4);
                ldsm_x4(ah[mt][0], ah[mt][1], ah[mt][2], ah[mt][3], ad);
                ldsm_x4(al[mt][0], al[mt][1], al[mt][2], al[mt][3], ad + 16384);
            }
            #pragma unroll
            for (int np = 0; np < 2; np++) {
                int row = wn + np * 16 + (lane >> 4) * 8 + (lane & 7);
                int seg = kk * 2 + ((lane >> 3) & 1);
                uint32_t ad = base + 32768 + row * 128 + ((seg ^ (row & 7)) << 4);
                ldsm_x4(bh[np*2][0], bh[np*2][1], bh[np*2+1][0], bh[np*2+1][1], ad);
                ldsm_x4(bl[np*2][0], bl[np*2][1], bl[np*2+1][0], bl[np*2+1][1], ad + 8192);
            }
            #pragma unroll
            for (int mt = 0; mt < 2; mt++)
                #pragma unroll
                for (int nf = 0; nf < 4; nf++) {
                    mma16816(acc[mt][nf], ah[mt], bh[nf]);
                    mma16816(acc[mt][nf], ah[mt], bl[nf]);
                    mma16816(acc[mt][nf], al[mt], bh[nf]);
                }
        }
        __syncthreads();
    }

    // epilogue: E = exp(-C/eps), F = E*C; stage E transposed in smem for ET.
    float* st = (float*)smem;                 // 64 cols x 132 floats = 33792 B
    #pragma unroll
    for (int mt = 0; mt < 2; mt++) {
        int lr0 = wm + mt * 16 + (lane >> 2);      // local row
        int r0 = i0 + lr0;
        float nx0 = g_nx[b * N_ + r0];
        float nx1 = g_nx[b * N_ + r0 + 8];
        #pragma unroll
        for (int nf = 0; nf < 4; nf++) {
            int lc0 = wn + nf * 8 + (lane & 3) * 2;
            int c0 = j0 + lc0;
            float ny0 = g_ny[b * M_ + c0];
            float ny1 = g_ny[b * M_ + c0 + 1];
            const float* a = acc[mt][nf];
            float C00 = 1.f - a[0] / fmaxf(nx0 * ny0, 1e-8f);
            float C01 = 1.f - a[1] / fmaxf(nx0 * ny1, 1e-8f);
            float C10 = 1.f - a[2] / fmaxf(nx1 * ny0, 1e-8f);
            float C11 = 1.f - a[3] / fmaxf(nx1 * ny1, 1e-8f);
            float e00 = __expf(-INV_EPS * C00);
            float e01 = __expf(-INV_EPS * C01);
            float e10 = __expf(-INV_EPS * C10);
            float e11 = __expf(-INV_EPS * C11);
            size_t ro0 = ((size_t)b * N_ + r0) * M_ + c0;
            size_t ro1 = ((size_t)b * N_ + r0 + 8) * M_ + c0;
            *(float2*)(g_E + ro0) = make_float2(e00, e01);
            *(float2*)(g_E + ro1) = make_float2(e10, e11);
            *(float2*)(g_F + ro0) = make_float2(e00 * C00, e01 * C01);
            *(float2*)(g_F + ro1) = make_float2(e10 * C10, e11 * C11);
            st[lc0 * 132 + lr0]           = e00;
            st[(lc0 + 1) * 132 + lr0]     = e01;
            st[lc0 * 132 + lr0 + 8]       = e10;
            st[(lc0 + 1) * 132 + lr0 + 8] = e11;
        }
    }
    __syncthreads();
    // ET tile: 64 rows (global cols j0..j0+63), each 128 floats at i0
    {
        int jj = tid >> 2;                  // 0..63
        int quarter = (tid & 3) * 32;
        float* dst = g_ET + ((size_t)b * M_ + j0 + jj) * N_ + i0 + quarter;
        const float* srcrow = st + jj * 132 + quarter;
        #pragma unroll
        for (int k = 0; k < 32; k += 4)
            *(float4*)(dst + k) = *(const float4*)(srcrow + k);
    }
}

// ---------------- persistent Sinkhorn kernel (1024 threads/CTA) ----------------
__device__ __forceinline__ void grid_sync_dev() {
    __syncthreads();
    if (threadIdx.x == 0) {
        int gen = g_gen;
        __threadfence();
        int prev = atomicAdd(&g_cnt, 1);
        if (prev == GRID_P - 1) {
            g_cnt = 0;
            __threadfence();
            g_gen = gen + 1;
        } else {
            while (g_gen == gen) { }
            __threadfence();
        }
    }
    __syncthreads();
}

__device__ __forceinline__ float dot_f32_row(const float4* erow, const float4* w, int lane) {
    float s = 0.f;
    #pragma unroll
    for (int p = 0; p < 8; p++) {
        float4 e = erow[p * 32 + lane];
        float4 wv = w[p * 32 + lane];
        s += e.x * wv.x + e.y * wv.y + e.z * wv.z + e.w * wv.w;
    }
    #pragma unroll
    for (int o = 16; o; o >>= 1) s += __shfl_down_sync(0xffffffffu, s, o);
    return s;
}

__global__ __launch_bounds__(SINK_T)
void sinkhorn_kernel(const float* __restrict__ nu, float* __restrict__ out) {
    const int t = threadIdx.x, wid = t >> 5, lane = t & 31;
    const int wgid = blockIdx.x * (SINK_T / 32) + wid;   // 0..SINK_W-1
    __shared__ float red[SINK_T];

    {   // init: v=0 -> bexp=1, u=0
        int gid = blockIdx.x * SINK_T + t;
        if (gid < B_ * M_) { g_bexp[gid] = 1.0f; g_u[gid] = 0.0f; }
    }
    grid_sync_dev();

    for (int it = 0; it < NITER; it++) {
        // ---- u update (~1 row per warp) ----
        for (int r = wgid; r < B_ * N_; r += SINK_W) {
            int b = r >> 10;
            float s = dot_f32_row((const float4*)(g_E + (size_t)r * M_),
                                  (const float4*)(g_bexp + (b << 10)), lane);
            if (lane == 0) {
                float u_new = EPS_F * (LOG_MU - __logf(s));
                g_errbuf[r] = fabsf(u_new - g_u[r]);
                g_u[r] = u_new;
                g_aexp[r] = MU_VAL / s;
            }
        }
        grid_sync_dev();   // publishes g_aexp AND g_errbuf

        // ---- err reduction (race-free window; identical in every CTA) ----
        float es = g_errbuf[t] + g_errbuf[t + 1024]
                 + g_errbuf[t + 2048] + g_errbuf[t + 3072];
        red[t] = es;
        __syncthreads();
        for (int o = SINK_T / 2; o; o >>= 1) {
            if (t < o) red[t] += red[t + o];
            __syncthreads();
        }
        float errv = red[0];
        __syncthreads();

        // ---- v update ----
        for (int c = wgid; c < B_ * M_; c += SINK_W) {
            int b = c >> 10;
            float s = dot_f32_row((const float4*)(g_ET + (size_t)c * N_),
                                  (const float4*)(g_aexp + (b << 10)), lane);
            if (lane == 0)
                g_bexp[c] = (__ldg(&nu[c]) + 1e-8f) / s;
        }
        grid_sync_dev();   // publishes g_bexp; fences errbuf from next writer

        // done-freeze: all remaining reference iterations are exact no-ops
        if (errv * 0.25f < THRESH_F) break;   // identical errv in all CTAs
    }

    // final cost: sum_i aexp_i * (sum_j F_ij * bexp_j),  F = E*C (exact C)
    for (int r = wgid; r < B_ * N_; r += SINK_W) {
        int b = r >> 10;
        float s = dot_f32_row((const float4*)(g_F + (size_t)r * M_),
                              (const float4*)(g_bexp + (b << 10)), lane);
        if (lane == 0) g_rowsum[r] = g_aexp[r] * s;
    }
    grid_sync_dev();
    if (blockIdx.x < B_) {
        int b = blockIdx.x;
        red[t] = g_rowsum[(b << 10) + t];
        __syncthreads();
        for (int o = 512; o; o >>= 1) {
            if (t < o) red[t] += red[t + o];
            __syncthreads();
        }
        if (t == 0) out[b] = red[0];
    }
}

// ---------------- launch ----------------
extern "C" void kernel_launch(void* const* d_in, const int* in_sizes, int n_in,
                              void* d_out, int out_size) {
    const float* x  = (const float*)d_in[0];
    const float* y  = (const float*)d_in[1];
    const float* nu = (const float*)d_in[2];
    float* out = (float*)d_out;

    cudaFuncSetAttribute(gemm_mma_kernel,
                         cudaFuncAttributeMaxDynamicSharedMemorySize, GEMM_SMEM);

    normsplit_kernel<<<B_ * N_ + B_ * M_, 128>>>(x, y);

    gemm_mma_kernel<<<dim3(16, 8, 4), 256, GEMM_SMEM>>>();

    sinkhorn_kernel<<<GRID_P, SINK_T>>>(nu, out);
}

// round 10
// speedup vs baseline: 4.5266x; 1.3671x over previous
#include <cuda_runtime.h>
#include <cuda_fp16.h>
#include <cstdint>
#include <math.h>

#define B_ 4
#define N_ 1024
#define M_ 1024
#define D_ 512
#define EPS_F 0.1f
#define INV_EPS 10.0f
#define THRESH_F 0.1f
#define LOG_MU -6.9314616f
#define MU_VAL (1.0f/1024.0f + 1e-8f)
#define NITER 20
#define GRID_P 148
#define SINK_T 1024
#define SINK_W (GRID_P * (SINK_T / 32))

// ---------------- scratch (no runtime allocation allowed) ----------------
__device__ float g_E [B_*N_*M_];    // fp32 exp(-C/eps), row-major
__device__ float g_ET[B_*N_*M_];    // fp32 transpose
__device__ float g_F [B_*N_*M_];    // fp32 E*C  (for final cost, no logf)
__device__ __half g_xh[B_*N_*D_];
__device__ __half g_yh[B_*M_*D_];
__device__ float g_nx[B_*N_], g_ny[B_*M_];
__device__ float g_u[B_*N_], g_aexp[B_*N_], g_bexp[B_*M_];
__device__ float g_errbuf[B_*N_], g_rowsum[B_*N_];
__device__ int g_cnt;
__device__ volatile int g_gen;

// ---------------- helpers ----------------
__device__ __forceinline__ uint32_t smem_u32(const void* p) {
    uint32_t a;
    asm("{ .reg .u64 t; cvta.to.shared.u64 t, %1; cvt.u32.u64 %0, t; }"
        : "=r"(a) : "l"(p));
    return a;
}

__device__ __forceinline__ void ldsm_x4(uint32_t& r0, uint32_t& r1,
                                        uint32_t& r2, uint32_t& r3, uint32_t addr) {
    asm volatile("ldmatrix.sync.aligned.m8n8.x4.shared.b16 {%0,%1,%2,%3}, [%4];"
        : "=r"(r0), "=r"(r1), "=r"(r2), "=r"(r3) : "r"(addr));
}

__device__ __forceinline__ void mma16816(float* d, const uint32_t* a, const uint32_t* b) {
    asm volatile("mma.sync.aligned.m16n8k16.row.col.f32.f16.f16.f32 "
        "{%0,%1,%2,%3}, {%4,%5,%6,%7}, {%8,%9}, {%0,%1,%2,%3};"
        : "+f"(d[0]), "+f"(d[1]), "+f"(d[2]), "+f"(d[3])
        : "r"(a[0]), "r"(a[1]), "r"(a[2]), "r"(a[3]), "r"(b[0]), "r"(b[1]));
}

#define CP_ASYNC16(dst, src) \
    asm volatile("cp.async.cg.shared.global [%0], [%1], 16;" \
                 :: "r"(dst), "l"(src) : "memory")
#define CP_COMMIT() asm volatile("cp.async.commit_group;" ::: "memory")
#define CP_WAIT1()  asm volatile("cp.async.wait_group 1;" ::: "memory")
#define CP_WAIT0()  asm volatile("cp.async.wait_group 0;" ::: "memory")

// ---------------- norms + fp16 convert (warp-per-row, single launch) -------
__global__ __launch_bounds__(256)
void normsplit_kernel(const float* __restrict__ x, const float* __restrict__ y) {
    int gw = (blockIdx.x * 256 + threadIdx.x) >> 5;   // global warp = row id
    int lane = threadIdx.x & 31;
    if (gw >= 2 * B_ * N_) return;
    const float* src; float* nrm; __half* dst; int row;
    if (gw < B_ * N_) { src = x; row = gw;            nrm = g_nx; dst = g_xh; }
    else              { src = y; row = gw - B_ * N_;  nrm = g_ny; dst = g_yh; }

    const float4* p = (const float4*)(src + (size_t)row * D_);
    uint2* drow = (uint2*)(dst + (size_t)row * D_);
    float s = 0.f;
    #pragma unroll
    for (int q = 0; q < 4; q++) {
        float4 a = p[lane + q * 32];
        s += a.x*a.x + a.y*a.y + a.z*a.z + a.w*a.w;
        __half2 h0 = __floats2half2_rn(a.x, a.y);
        __half2 h1 = __floats2half2_rn(a.z, a.w);
        uint2 pk;
        pk.x = *(const uint32_t*)&h0;
        pk.y = *(const uint32_t*)&h1;
        drow[lane + q * 32] = pk;
    }
    #pragma unroll
    for (int o = 16; o; o >>= 1) s += __shfl_down_sync(0xffffffffu, s, o);
    if (lane == 0) nrm[row] = sqrtf(s);
}

// ---------------- mma.sync fp16 single-pass GEMM, 128x64 tiles -------------
// stage layout: A @0 (16KB), B @16384 (8KB); 24KB/stage, 2 stages = 48KB/CTA.
#define GS_STAGE 24576
#define GEMM_SMEM (2 * GS_STAGE)

__global__ __launch_bounds__(256, 3)
void gemm_mma_kernel() {
    extern __shared__ char smem[];
    const int tid = threadIdx.x;
    const int wid = tid >> 5, lane = tid & 31;
    const int b = blockIdx.z, i0 = blockIdx.y * 128, j0 = blockIdx.x * 64;
    const int wm = (wid & 3) * 32;      // warp row offset (0..96)
    const int wn = (wid >> 2) * 32;     // warp col offset (0 or 32)
    uint32_t sb = smem_u32(smem);

    const __half* Axh = g_xh + ((size_t)b * N_ + i0) * D_;
    const __half* Byh = g_yh + ((size_t)b * M_ + j0) * D_;

    auto stage_load = [&](int c, int s) {
        uint32_t tb = sb + s * GS_STAGE;
        #pragma unroll
        for (int q = 0; q < 4; q++) {
            int idx = q * 256 + tid;            // A: 1024 chunks
            int row = idx >> 3, cc = idx & 7;
            uint32_t off = row * 128 + ((cc ^ (row & 7)) << 4);
            const __half* g = Axh + (size_t)row * D_ + c * 64 + cc * 8;
            CP_ASYNC16(tb + off, (const void*)__cvta_generic_to_global(g));
        }
        #pragma unroll
        for (int q = 0; q < 2; q++) {
            int idx = q * 256 + tid;            // B: 512 chunks
            int row = idx >> 3, cc = idx & 7;
            uint32_t off = row * 128 + ((cc ^ (row & 7)) << 4);
            const __half* g = Byh + (size_t)row * D_ + c * 64 + cc * 8;
            CP_ASYNC16(tb + 16384 + off, (const void*)__cvta_generic_to_global(g));
        }
    };

    float acc[2][4][4];
    #pragma unroll
    for (int mt = 0; mt < 2; mt++)
        #pragma unroll
        for (int nf = 0; nf < 4; nf++)
            #pragma unroll
            for (int q = 0; q < 4; q++) acc[mt][nf][q] = 0.f;

    stage_load(0, 0);
    CP_COMMIT();

    for (int c = 0; c < 8; c++) {
        if (c < 7) { stage_load(c + 1, (c + 1) & 1); CP_COMMIT(); CP_WAIT1(); }
        else       { CP_WAIT0(); }
        __syncthreads();

        uint32_t base = sb + (c & 1) * GS_STAGE;
        #pragma unroll
        for (int kk = 0; kk < 4; kk++) {
            uint32_t ah[2][4], bh[4][2];
            #pragma unroll
            for (int mt = 0; mt < 2; mt++) {
                int row = wm + mt * 16 + ((lane >> 3) & 1) * 8 + (lane & 7);
                int seg = kk * 2 + (lane >> 4);
                uint32_t ad = base + row * 128 + ((seg ^ (row & 7)) << 4);
                ldsm_x4(ah[mt][0], ah[mt][1], ah[mt][2], ah[mt][3], ad);
            }
            #pragma unroll
            for (int np = 0; np < 2; np++) {
                int row = wn + np * 16 + (lane >> 4) * 8 + (lane & 7);
                int seg = kk * 2 + ((lane >> 3) & 1);
                uint32_t ad = base + 16384 + row * 128 + ((seg ^ (row & 7)) << 4);
                ldsm_x4(bh[np*2][0], bh[np*2][1], bh[np*2+1][0], bh[np*2+1][1], ad);
            }
            #pragma unroll
            for (int mt = 0; mt < 2; mt++)
                #pragma unroll
                for (int nf = 0; nf < 4; nf++)
                    mma16816(acc[mt][nf], ah[mt], bh[nf]);
        }
        __syncthreads();
    }

    // epilogue: E = exp(-C/eps), F = E*C; stage E transposed in smem for ET.
    float* st = (float*)smem;                 // 64 cols x 132 floats = 33792 B
    #pragma unroll
    for (int mt = 0; mt < 2; mt++) {
        int lr0 = wm + mt * 16 + (lane >> 2);      // local row
        int r0 = i0 + lr0;
        float nx0 = g_nx[b * N_ + r0];
        float nx1 = g_nx[b * N_ + r0 + 8];
        #pragma unroll
        for (int nf = 0; nf < 4; nf++) {
            int lc0 = wn + nf * 8 + (lane & 3) * 2;
            int c0 = j0 + lc0;
            float ny0 = g_ny[b * M_ + c0];
            float ny1 = g_ny[b * M_ + c0 + 1];
            const float* a = acc[mt][nf];
            float C00 = 1.f - a[0] / fmaxf(nx0 * ny0, 1e-8f);
            float C01 = 1.f - a[1] / fmaxf(nx0 * ny1, 1e-8f);
            float C10 = 1.f - a[2] / fmaxf(nx1 * ny0, 1e-8f);
            float C11 = 1.f - a[3] / fmaxf(nx1 * ny1, 1e-8f);
            float e00 = __expf(-INV_EPS * C00);
            float e01 = __expf(-INV_EPS * C01);
            float e10 = __expf(-INV_EPS * C10);
            float e11 = __expf(-INV_EPS * C11);
            size_t ro0 = ((size_t)b * N_ + r0) * M_ + c0;
            size_t ro1 = ((size_t)b * N_ + r0 + 8) * M_ + c0;
            *(float2*)(g_E + ro0) = make_float2(e00, e01);
            *(float2*)(g_E + ro1) = make_float2(e10, e11);
            *(float2*)(g_F + ro0) = make_float2(e00 * C00, e01 * C01);
            *(float2*)(g_F + ro1) = make_float2(e10 * C10, e11 * C11);
            st[lc0 * 132 + lr0]           = e00;
            st[(lc0 + 1) * 132 + lr0]     = e01;
            st[lc0 * 132 + lr0 + 8]       = e10;
            st[(lc0 + 1) * 132 + lr0 + 8] = e11;
        }
    }
    __syncthreads();
    // ET tile: 64 rows (global cols j0..j0+63), each 128 floats at i0
    {
        int jj = tid >> 2;                  // 0..63
        int quarter = (tid & 3) * 32;
        float* dst = g_ET + ((size_t)b * M_ + j0 + jj) * N_ + i0 + quarter;
        const float* srcrow = st + jj * 132 + quarter;
        #pragma unroll
        for (int k = 0; k < 32; k += 4)
            *(float4*)(dst + k) = *(const float4*)(srcrow + k);
    }
}

// ---------------- persistent Sinkhorn kernel (1024 threads/CTA) ----------------
__device__ __forceinline__ void grid_sync_dev() {
    __syncthreads();
    if (threadIdx.x == 0) {
        int gen = g_gen;
        __threadfence();
        int prev = atomicAdd(&g_cnt, 1);
        if (prev == GRID_P - 1) {
            g_cnt = 0;
            __threadfence();
            g_gen = gen + 1;
        } else {
            while (g_gen == gen) { }
            __threadfence();
        }
    }
    __syncthreads();
}

__device__ __forceinline__ float dot_f32_row(const float4* erow, const float4* w, int lane) {
    float s = 0.f;
    #pragma unroll
    for (int p = 0; p < 8; p++) {
        float4 e = erow[p * 32 + lane];
        float4 wv = w[p * 32 + lane];
        s += e.x * wv.x + e.y * wv.y + e.z * wv.z + e.w * wv.w;
    }
    #pragma unroll
    for (int o = 16; o; o >>= 1) s += __shfl_down_sync(0xffffffffu, s, o);
    return s;
}

__global__ __launch_bounds__(SINK_T)
void sinkhorn_kernel(const float* __restrict__ nu, float* __restrict__ out) {
    const int t = threadIdx.x, wid = t >> 5, lane = t & 31;
    const int wgid = blockIdx.x * (SINK_T / 32) + wid;   // 0..SINK_W-1
    __shared__ float red[SINK_T];

    {   // init: v=0 -> bexp=1, u=0
        int gid = blockIdx.x * SINK_T + t;
        if (gid < B_ * M_) { g_bexp[gid] = 1.0f; g_u[gid] = 0.0f; }
    }
    grid_sync_dev();

    for (int it = 0; it < NITER; it++) {
        // ---- u update (~1 row per warp) ----
        for (int r = wgid; r < B_ * N_; r += SINK_W) {
            int b = r >> 10;
            float s = dot_f32_row((const float4*)(g_E + (size_t)r * M_),
                                  (const float4*)(g_bexp + (b << 10)), lane);
            if (lane == 0) {
                float u_new = EPS_F * (LOG_MU - __logf(s));
                g_errbuf[r] = fabsf(u_new - g_u[r]);
                g_u[r] = u_new;
                g_aexp[r] = MU_VAL / s;
            }
        }
        grid_sync_dev();   // publishes g_aexp AND g_errbuf

        // ---- err reduction (race-free window; identical in every CTA) ----
        float es = g_errbuf[t] + g_errbuf[t + 1024]
                 + g_errbuf[t + 2048] + g_errbuf[t + 3072];
        red[t] = es;
        __syncthreads();
        for (int o = SINK_T / 2; o; o >>= 1) {
            if (t < o) red[t] += red[t + o];
            __syncthreads();
        }
        float errv = red[0];
        __syncthreads();

        // ---- v update ----
        for (int c = wgid; c < B_ * M_; c += SINK_W) {
            int b = c >> 10;
            float s = dot_f32_row((const float4*)(g_ET + (size_t)c * N_),
                                  (const float4*)(g_aexp + (b << 10)), lane);
            if (lane == 0)
                g_bexp[c] = (__ldg(&nu[c]) + 1e-8f) / s;
        }
        grid_sync_dev();   // publishes g_bexp; fences errbuf from next writer

        // done-freeze: all remaining reference iterations are exact no-ops
        if (errv * 0.25f < THRESH_F) break;   // identical errv in all CTAs
    }

    // final cost: sum_i aexp_i * (sum_j F_ij * bexp_j),  F = E*C (exact C)
    for (int r = wgid; r < B_ * N_; r += SINK_W) {
        int b = r >> 10;
        float s = dot_f32_row((const float4*)(g_F + (size_t)r * M_),
                              (const float4*)(g_bexp + (b << 10)), lane);
        if (lane == 0) g_rowsum[r] = g_aexp[r] * s;
    }
    grid_sync_dev();
    if (blockIdx.x < B_) {
        int b = blockIdx.x;
        red[t] = g_rowsum[(b << 10) + t];
        __syncthreads();
        for (int o = 512; o; o >>= 1) {
            if (t < o) red[t] += red[t + o];
            __syncthreads();
        }
        if (t == 0) out[b] = red[0];
    }
}

// ---------------- launch ----------------
extern "C" void kernel_launch(void* const* d_in, const int* in_sizes, int n_in,
                              void* d_out, int out_size) {
    const float* x  = (const float*)d_in[0];
    const float* y  = (const float*)d_in[1];
    const float* nu = (const float*)d_in[2];
    float* out = (float*)d_out;

    cudaFuncSetAttribute(gemm_mma_kernel,
                         cudaFuncAttributeMaxDynamicSharedMemorySize, GEMM_SMEM);

    normsplit_kernel<<<(2 * B_ * N_ * 32 + 255) / 256, 256>>>(x, y);

    gemm_mma_kernel<<<dim3(16, 8, 4), 256, GEMM_SMEM>>>();

    sinkhorn_kernel<<<GRID_P, SINK_T>>>(nu, out);
}

// round 11
// speedup vs baseline: 4.9621x; 1.0962x over previous
#include <cuda_runtime.h>
#include <cuda_fp16.h>
#include <cuda_bf16.h>
#include <cstdint>
#include <math.h>

#define B_ 4
#define N_ 1024
#define M_ 1024
#define D_ 512
#define EPS_F 0.1f
#define INV_EPS 10.0f
#define THRESH_F 0.1f
#define LOG_MU -6.9314616f
#define MU_VAL (1.0f/1024.0f + 1e-8f)
#define NITER 20
#define GRID_P 148
#define SINK_T 1024
#define SINK_W (GRID_P * (SINK_T / 32))

// ---------------- scratch (no runtime allocation allowed) ----------------
__device__ __nv_bfloat16 g_Ebf [B_*N_*M_];   // bf16 exp(-C/eps), row-major
__device__ __nv_bfloat16 g_ETbf[B_*N_*M_];   // bf16 transpose
__device__ __half g_xh[B_*N_*D_];
__device__ __half g_yh[B_*M_*D_];
__device__ float g_nx[B_*N_], g_ny[B_*M_];
__device__ float g_u[B_*N_], g_aexp[B_*N_], g_bexp[B_*M_];
__device__ float g_errbuf[B_*N_], g_rowsum[B_*N_];
__device__ int g_cnt;
__device__ volatile int g_gen;

// ---------------- helpers ----------------
__device__ __forceinline__ uint32_t smem_u32(const void* p) {
    uint32_t a;
    asm("{ .reg .u64 t; cvta.to.shared.u64 t, %1; cvt.u32.u64 %0, t; }"
        : "=r"(a) : "l"(p));
    return a;
}

__device__ __forceinline__ void ldsm_x4(uint32_t& r0, uint32_t& r1,
                                        uint32_t& r2, uint32_t& r3, uint32_t addr) {
    asm volatile("ldmatrix.sync.aligned.m8n8.x4.shared.b16 {%0,%1,%2,%3}, [%4];"
        : "=r"(r0), "=r"(r1), "=r"(r2), "=r"(r3) : "r"(addr));
}

__device__ __forceinline__ void mma16816(float* d, const uint32_t* a, const uint32_t* b) {
    asm volatile("mma.sync.aligned.m16n8k16.row.col.f32.f16.f16.f32 "
        "{%0,%1,%2,%3}, {%4,%5,%6,%7}, {%8,%9}, {%0,%1,%2,%3};"
        : "+f"(d[0]), "+f"(d[1]), "+f"(d[2]), "+f"(d[3])
        : "r"(a[0]), "r"(a[1]), "r"(a[2]), "r"(a[3]), "r"(b[0]), "r"(b[1]));
}

#define CP_ASYNC16(dst, src) \
    asm volatile("cp.async.cg.shared.global [%0], [%1], 16;" \
                 :: "r"(dst), "l"(src) : "memory")
#define CP_COMMIT() asm volatile("cp.async.commit_group;" ::: "memory")
#define CP_WAIT1()  asm volatile("cp.async.wait_group 1;" ::: "memory")
#define CP_WAIT0()  asm volatile("cp.async.wait_group 0;" ::: "memory")

// ---------------- norms + fp16 convert (warp-per-row, single launch) -------
__global__ __launch_bounds__(256)
void normsplit_kernel(const float* __restrict__ x, const float* __restrict__ y) {
    int gw = (blockIdx.x * 256 + threadIdx.x) >> 5;   // global warp = row id
    int lane = threadIdx.x & 31;
    if (gw >= 2 * B_ * N_) return;
    const float* src; float* nrm; __half* dst; int row;
    if (gw < B_ * N_) { src = x; row = gw;            nrm = g_nx; dst = g_xh; }
    else              { src = y; row = gw - B_ * N_;  nrm = g_ny; dst = g_yh; }

    const float4* p = (const float4*)(src + (size_t)row * D_);
    uint2* drow = (uint2*)(dst + (size_t)row * D_);
    float s = 0.f;
    #pragma unroll
    for (int q = 0; q < 4; q++) {
        float4 a = p[lane + q * 32];
        s += a.x*a.x + a.y*a.y + a.z*a.z + a.w*a.w;
        __half2 h0 = __floats2half2_rn(a.x, a.y);
        __half2 h1 = __floats2half2_rn(a.z, a.w);
        uint2 pk;
        pk.x = *(const uint32_t*)&h0;
        pk.y = *(const uint32_t*)&h1;
        drow[lane + q * 32] = pk;
    }
    #pragma unroll
    for (int o = 16; o; o >>= 1) s += __shfl_down_sync(0xffffffffu, s, o);
    if (lane == 0) nrm[row] = sqrtf(s);
}

// ---------------- mma.sync fp16 single-pass GEMM, 128x64 tiles -------------
// stage layout: A @0 (16KB), B @16384 (8KB); 24KB/stage, 2 stages = 48KB/CTA.
#define GS_STAGE 24576
#define GEMM_SMEM (2 * GS_STAGE)
#define ST_S 136   // staging stride (bf16 elems per column; 16B-aligned)

__global__ __launch_bounds__(256, 3)
void gemm_mma_kernel() {
    extern __shared__ char smem[];
    const int tid = threadIdx.x;
    const int wid = tid >> 5, lane = tid & 31;
    const int b = blockIdx.z, i0 = blockIdx.y * 128, j0 = blockIdx.x * 64;
    const int wm = (wid & 3) * 32;      // warp row offset (0..96)
    const int wn = (wid >> 2) * 32;     // warp col offset (0 or 32)
    uint32_t sb = smem_u32(smem);

    const __half* Axh = g_xh + ((size_t)b * N_ + i0) * D_;
    const __half* Byh = g_yh + ((size_t)b * M_ + j0) * D_;

    auto stage_load = [&](int c, int s) {
        uint32_t tb = sb + s * GS_STAGE;
        #pragma unroll
        for (int q = 0; q < 4; q++) {
            int idx = q * 256 + tid;            // A: 1024 chunks
            int row = idx >> 3, cc = idx & 7;
            uint32_t off = row * 128 + ((cc ^ (row & 7)) << 4);
            const __half* g = Axh + (size_t)row * D_ + c * 64 + cc * 8;
            CP_ASYNC16(tb + off, (const void*)__cvta_generic_to_global(g));
        }
        #pragma unroll
        for (int q = 0; q < 2; q++) {
            int idx = q * 256 + tid;            // B: 512 chunks
            int row = idx >> 3, cc = idx & 7;
            uint32_t off = row * 128 + ((cc ^ (row & 7)) << 4);
            const __half* g = Byh + (size_t)row * D_ + c * 64 + cc * 8;
            CP_ASYNC16(tb + 16384 + off, (const void*)__cvta_generic_to_global(g));
        }
    };

    float acc[2][4][4];
    #pragma unroll
    for (int mt = 0; mt < 2; mt++)
        #pragma unroll
        for (int nf = 0; nf < 4; nf++)
            #pragma unroll
            for (int q = 0; q < 4; q++) acc[mt][nf][q] = 0.f;

    stage_load(0, 0);
    CP_COMMIT();

    for (int c = 0; c < 8; c++) {
        if (c < 7) { stage_load(c + 1, (c + 1) & 1); CP_COMMIT(); CP_WAIT1(); }
        else       { CP_WAIT0(); }
        __syncthreads();

        uint32_t base = sb + (c & 1) * GS_STAGE;
        #pragma unroll
        for (int kk = 0; kk < 4; kk++) {
            uint32_t ah[2][4], bh[4][2];
            #pragma unroll
            for (int mt = 0; mt < 2; mt++) {
                int row = wm + mt * 16 + ((lane >> 3) & 1) * 8 + (lane & 7);
                int seg = kk * 2 + (lane >> 4);
                uint32_t ad = base + row * 128 + ((seg ^ (row & 7)) << 4);
                ldsm_x4(ah[mt][0], ah[mt][1], ah[mt][2], ah[mt][3], ad);
            }
            #pragma unroll
            for (int np = 0; np < 2; np++) {
                int row = wn + np * 16 + (lane >> 4) * 8 + (lane & 7);
                int seg = kk * 2 + ((lane >> 3) & 1);
                uint32_t ad = base + 16384 + row * 128 + ((seg ^ (row & 7)) << 4);
                ldsm_x4(bh[np*2][0], bh[np*2][1], bh[np*2+1][0], bh[np*2+1][1], ad);
            }
            #pragma unroll
            for (int mt = 0; mt < 2; mt++)
                #pragma unroll
                for (int nf = 0; nf < 4; nf++)
                    mma16816(acc[mt][nf], ah[mt], bh[nf]);
        }
        __syncthreads();
    }

    // epilogue: E = exp(-C/eps) -> bf16; stage E transposed in smem for ET.
    __nv_bfloat16* st16 = (__nv_bfloat16*)smem;   // 64 cols x ST_S = 17408 B
    #pragma unroll
    for (int mt = 0; mt < 2; mt++) {
        int lr0 = wm + mt * 16 + (lane >> 2);      // local row
        int r0 = i0 + lr0;
        float nx0 = g_nx[b * N_ + r0];
        float nx1 = g_nx[b * N_ + r0 + 8];
        #pragma unroll
        for (int nf = 0; nf < 4; nf++) {
            int lc0 = wn + nf * 8 + (lane & 3) * 2;
            int c0 = j0 + lc0;
            float ny0 = g_ny[b * M_ + c0];
            float ny1 = g_ny[b * M_ + c0 + 1];
            const float* a = acc[mt][nf];
            float C00 = 1.f - a[0] / fmaxf(nx0 * ny0, 1e-8f);
            float C01 = 1.f - a[1] / fmaxf(nx0 * ny1, 1e-8f);
            float C10 = 1.f - a[2] / fmaxf(nx1 * ny0, 1e-8f);
            float C11 = 1.f - a[3] / fmaxf(nx1 * ny1, 1e-8f);
            __nv_bfloat16 e00 = __float2bfloat16(__expf(-INV_EPS * C00));
            __nv_bfloat16 e01 = __float2bfloat16(__expf(-INV_EPS * C01));
            __nv_bfloat16 e10 = __float2bfloat16(__expf(-INV_EPS * C10));
            __nv_bfloat16 e11 = __float2bfloat16(__expf(-INV_EPS * C11));
            size_t ro0 = ((size_t)b * N_ + r0) * M_ + c0;
            size_t ro1 = ((size_t)b * N_ + r0 + 8) * M_ + c0;
            *(__nv_bfloat162*)(g_Ebf + ro0) = __halves2bfloat162(e00, e01);
            *(__nv_bfloat162*)(g_Ebf + ro1) = __halves2bfloat162(e10, e11);
            st16[lc0 * ST_S + lr0]           = e00;
            st16[(lc0 + 1) * ST_S + lr0]     = e01;
            st16[lc0 * ST_S + lr0 + 8]       = e10;
            st16[(lc0 + 1) * ST_S + lr0 + 8] = e11;
        }
    }
    __syncthreads();
    // ET tile: 64 rows (global cols j0..j0+63), each 128 bf16 at i0
    {
        int jj = tid >> 2;                  // 0..63
        int quarter = (tid & 3) * 32;       // 32 bf16 = 64 bytes
        __nv_bfloat16* dst = g_ETbf + ((size_t)b * M_ + j0 + jj) * N_ + i0 + quarter;
        const __nv_bfloat16* srcrow = st16 + jj * ST_S + quarter;
        #pragma unroll
        for (int k = 0; k < 32; k += 8)
            *(uint4*)(dst + k) = *(const uint4*)(srcrow + k);
    }
}

// ---------------- persistent Sinkhorn kernel (1024 threads/CTA) ----------------
__device__ __forceinline__ void grid_sync_dev() {
    __syncthreads();
    if (threadIdx.x == 0) {
        int gen = g_gen;
        __threadfence();
        int prev = atomicAdd(&g_cnt, 1);
        if (prev == GRID_P - 1) {
            g_cnt = 0;
            __threadfence();
            g_gen = gen + 1;
        } else {
            while (g_gen == gen) { }
            __threadfence();
        }
    }
    __syncthreads();
}

// dot over one bf16 row (1024 elems = 128 uint4) with fp32 weights
__device__ __forceinline__ float dot_bf_row(const uint4* erow, const float4* w, int lane) {
    float s = 0.f;
    #pragma unroll
    for (int p = 0; p < 4; p++) {
        uint4 e = erow[p * 32 + lane];
        float4 w0 = w[(p * 32 + lane) * 2];
        float4 w1 = w[(p * 32 + lane) * 2 + 1];
        float2 f0 = __bfloat1622float2(*(__nv_bfloat162*)&e.x);
        float2 f1 = __bfloat1622float2(*(__nv_bfloat162*)&e.y);
        float2 f2 = __bfloat1622float2(*(__nv_bfloat162*)&e.z);
        float2 f3 = __bfloat1622float2(*(__nv_bfloat162*)&e.w);
        s += f0.x * w0.x + f0.y * w0.y + f1.x * w0.z + f1.y * w0.w
           + f2.x * w1.x + f2.y * w1.y + f3.x * w1.z + f3.y * w1.w;
    }
    #pragma unroll
    for (int o = 16; o; o >>= 1) s += __shfl_down_sync(0xffffffffu, s, o);
    return s;
}

__global__ __launch_bounds__(SINK_T)
void sinkhorn_kernel(const float* __restrict__ nu, float* __restrict__ out) {
    const int t = threadIdx.x, wid = t >> 5, lane = t & 31;
    const int wgid = blockIdx.x * (SINK_T / 32) + wid;   // 0..SINK_W-1
    __shared__ float red[SINK_T];

    {   // init: v=0 -> bexp=1, u=0
        int gid = blockIdx.x * SINK_T + t;
        if (gid < B_ * M_) { g_bexp[gid] = 1.0f; g_u[gid] = 0.0f; }
    }
    grid_sync_dev();

    for (int it = 0; it < NITER; it++) {
        // ---- u update (~1 row per warp) ----
        for (int r = wgid; r < B_ * N_; r += SINK_W) {
            int b = r >> 10;
            float s = dot_bf_row((const uint4*)(g_Ebf + (size_t)r * M_),
                                 (const float4*)(g_bexp + (b << 10)), lane);
            if (lane == 0) {
                float u_new = EPS_F * (LOG_MU - __logf(s));
                g_errbuf[r] = fabsf(u_new - g_u[r]);
                g_u[r] = u_new;
                g_aexp[r] = MU_VAL / s;
            }
        }
        grid_sync_dev();   // publishes g_aexp AND g_errbuf

        // ---- err reduction (race-free window; identical in every CTA) ----
        float es = g_errbuf[t] + g_errbuf[t + 1024]
                 + g_errbuf[t + 2048] + g_errbuf[t + 3072];
        red[t] = es;
        __syncthreads();
        for (int o = SINK_T / 2; o; o >>= 1) {
            if (t < o) red[t] += red[t + o];
            __syncthreads();
        }
        float errv = red[0];
        __syncthreads();

        // ---- v update ----
        for (int c = wgid; c < B_ * M_; c += SINK_W) {
            int b = c >> 10;
            float s = dot_bf_row((const uint4*)(g_ETbf + (size_t)c * N_),
                                 (const float4*)(g_aexp + (b << 10)), lane);
            if (lane == 0)
                g_bexp[c] = (__ldg(&nu[c]) + 1e-8f) / s;
        }
        grid_sync_dev();   // publishes g_bexp; fences errbuf from next writer

        // done-freeze: all remaining reference iterations are exact no-ops
        if (errv * 0.25f < THRESH_F) break;   // identical errv in all CTAs
    }

    // final cost: sum_i aexp_i * (sum_j E_ij*bexp_j*C_ij), C = -eps*ln(E)
    for (int r = wgid; r < B_ * N_; r += SINK_W) {
        int b = r >> 10;
        const uint4* erow = (const uint4*)(g_Ebf + (size_t)r * M_);
        const float4* w = (const float4*)(g_bexp + (b << 10));
        float s = 0.f;
        #pragma unroll
        for (int p = 0; p < 4; p++) {
            uint4 e = erow[p * 32 + lane];
            float4 w0 = w[(p * 32 + lane) * 2];
            float4 w1 = w[(p * 32 + lane) * 2 + 1];
            float2 f0 = __bfloat1622float2(*(__nv_bfloat162*)&e.x);
            float2 f1 = __bfloat1622float2(*(__nv_bfloat162*)&e.y);
            float2 f2 = __bfloat1622float2(*(__nv_bfloat162*)&e.z);
            float2 f3 = __bfloat1622float2(*(__nv_bfloat162*)&e.w);
            s += f0.x * w0.x * __logf(f0.x) + f0.y * w0.y * __logf(f0.y)
               + f1.x * w0.z * __logf(f1.x) + f1.y * w0.w * __logf(f1.y)
               + f2.x * w1.x * __logf(f2.x) + f2.y * w1.y * __logf(f2.y)
               + f3.x * w1.z * __logf(f3.x) + f3.y * w1.w * __logf(f3.y);
        }
        #pragma unroll
        for (int o = 16; o; o >>= 1) s += __shfl_down_sync(0xffffffffu, s, o);
        if (lane == 0) g_rowsum[r] = g_aexp[r] * s * (-EPS_F);
    }
    grid_sync_dev();
    if (blockIdx.x < B_) {
        int b = blockIdx.x;
        red[t] = g_rowsum[(b << 10) + t];
        __syncthreads();
        for (int o = 512; o; o >>= 1) {
            if (t < o) red[t] += red[t + o];
            __syncthreads();
        }
        if (t == 0) out[b] = red[0];
    }
}

// ---------------- launch ----------------
extern "C" void kernel_launch(void* const* d_in, const int* in_sizes, int n_in,
                              void* d_out, int out_size) {
    const float* x  = (const float*)d_in[0];
    const float* y  = (const float*)d_in[1];
    const float* nu = (const float*)d_in[2];
    float* out = (float*)d_out;

    cudaFuncSetAttribute(gemm_mma_kernel,
                         cudaFuncAttributeMaxDynamicSharedMemorySize, GEMM_SMEM);

    normsplit_kernel<<<(2 * B_ * N_ * 32 + 255) / 256, 256>>>(x, y);

    gemm_mma_kernel<<<dim3(16, 8, 4), 256, GEMM_SMEM>>>();

    sinkhorn_kernel<<<GRID_P, SINK_T>>>(nu, out);
}

// round 12
// speedup vs baseline: 5.1406x; 1.0360x over previous
#include <cuda_runtime.h>
#include <cuda_fp16.h>
#include <cuda_bf16.h>
#include <cstdint>
#include <math.h>

#define B_ 4
#define N_ 1024
#define M_ 1024
#define D_ 512
#define EPS_F 0.1f
#define INV_EPS 10.0f
#define THRESH_F 0.1f
#define LOG_MU -6.9314616f
#define MU_VAL (1.0f/1024.0f + 1e-8f)
#define NITER 20
#define GRID_P 148
#define SINK_T 1024
#define SINK_W (GRID_P * (SINK_T / 32))

// ---------------- scratch (no runtime allocation allowed) ----------------
__device__ __nv_bfloat16 g_Ebf [B_*N_*M_];   // bf16 exp(-C/eps), row-major
__device__ __nv_bfloat16 g_ETbf[B_*N_*M_];   // bf16 transpose
__device__ __half g_xh[B_*N_*D_];
__device__ __half g_yh[B_*M_*D_];
__device__ float g_nx[B_*N_], g_ny[B_*M_];
__device__ float g_u[B_*N_], g_aexp[B_*N_], g_bexp[B_*M_];
__device__ float g_errbuf[B_*N_], g_rowsum[B_*N_];
__device__ int g_cnt;
__device__ int g_gen;

// ---------------- helpers ----------------
__device__ __forceinline__ uint32_t smem_u32(const void* p) {
    uint32_t a;
    asm("{ .reg .u64 t; cvta.to.shared.u64 t, %1; cvt.u32.u64 %0, t; }"
        : "=r"(a) : "l"(p));
    return a;
}

__device__ __forceinline__ void ldsm_x4(uint32_t& r0, uint32_t& r1,
                                        uint32_t& r2, uint32_t& r3, uint32_t addr) {
    asm volatile("ldmatrix.sync.aligned.m8n8.x4.shared.b16 {%0,%1,%2,%3}, [%4];"
        : "=r"(r0), "=r"(r1), "=r"(r2), "=r"(r3) : "r"(addr));
}

__device__ __forceinline__ void mma16816(float* d, const uint32_t* a, const uint32_t* b) {
    asm volatile("mma.sync.aligned.m16n8k16.row.col.f32.f16.f16.f32 "
        "{%0,%1,%2,%3}, {%4,%5,%6,%7}, {%8,%9}, {%0,%1,%2,%3};"
        : "+f"(d[0]), "+f"(d[1]), "+f"(d[2]), "+f"(d[3])
        : "r"(a[0]), "r"(a[1]), "r"(a[2]), "r"(a[3]), "r"(b[0]), "r"(b[1]));
}

#define CP_ASYNC16(dst, src) \
    asm volatile("cp.async.cg.shared.global [%0], [%1], 16;" \
                 :: "r"(dst), "l"(src) : "memory")
#define CP_COMMIT() asm volatile("cp.async.commit_group;" ::: "memory")
#define CP_WAIT1()  asm volatile("cp.async.wait_group 1;" ::: "memory")
#define CP_WAIT0()  asm volatile("cp.async.wait_group 0;" ::: "memory")

// ---------------- norms + fp16 convert: 2 rows per warp, batched loads ------
__global__ __launch_bounds__(256)
void normsplit_kernel(const float* __restrict__ x, const float* __restrict__ y) {
    int gw = (blockIdx.x * 256 + threadIdx.x) >> 5;   // warp id; handles rows 2gw, 2gw+1
    int lane = threadIdx.x & 31;
    int row0 = gw * 2;
    if (row0 >= 2 * B_ * N_) return;
    const float* src; float* nrm; __half* dst; int rbase;
    if (row0 < B_ * N_) { src = x; rbase = row0;            nrm = g_nx; dst = g_xh; }
    else                { src = y; rbase = row0 - B_ * N_;  nrm = g_ny; dst = g_yh; }

    const float4* p0 = (const float4*)(src + (size_t)rbase * D_);
    const float4* p1 = p0 + D_ / 4;
    float4 a0[4], a1[4];
    #pragma unroll
    for (int q = 0; q < 4; q++) { a0[q] = p0[lane + q * 32]; a1[q] = p1[lane + q * 32]; }

    uint2* d0 = (uint2*)(dst + (size_t)rbase * D_);
    uint2* d1 = d0 + D_ / 4;
    float s0 = 0.f, s1 = 0.f;
    #pragma unroll
    for (int q = 0; q < 4; q++) {
        s0 += a0[q].x*a0[q].x + a0[q].y*a0[q].y + a0[q].z*a0[q].z + a0[q].w*a0[q].w;
        s1 += a1[q].x*a1[q].x + a1[q].y*a1[q].y + a1[q].z*a1[q].z + a1[q].w*a1[q].w;
        __half2 h00 = __floats2half2_rn(a0[q].x, a0[q].y);
        __half2 h01 = __floats2half2_rn(a0[q].z, a0[q].w);
        __half2 h10 = __floats2half2_rn(a1[q].x, a1[q].y);
        __half2 h11 = __floats2half2_rn(a1[q].z, a1[q].w);
        uint2 k0, k1;
        k0.x = *(const uint32_t*)&h00; k0.y = *(const uint32_t*)&h01;
        k1.x = *(const uint32_t*)&h10; k1.y = *(const uint32_t*)&h11;
        d0[lane + q * 32] = k0;
        d1[lane + q * 32] = k1;
    }
    #pragma unroll
    for (int o = 16; o; o >>= 1) {
        s0 += __shfl_down_sync(0xffffffffu, s0, o);
        s1 += __shfl_down_sync(0xffffffffu, s1, o);
    }
    if (lane == 0) { nrm[rbase] = sqrtf(s0); nrm[rbase + 1] = sqrtf(s1); }
}

// ---------------- mma.sync fp16 single-pass GEMM, 128x64 tiles -------------
// stage layout: A @0 (16KB), B @16384 (8KB); 24KB/stage, 2 stages = 48KB/CTA.
#define GS_STAGE 24576
#define GEMM_SMEM (2 * GS_STAGE)
#define ST_S 136   // staging stride (bf16 elems per column; 16B-aligned)

__global__ __launch_bounds__(256, 3)
void gemm_mma_kernel() {
    extern __shared__ char smem[];
    const int tid = threadIdx.x;
    const int wid = tid >> 5, lane = tid & 31;
    const int b = blockIdx.z, i0 = blockIdx.y * 128, j0 = blockIdx.x * 64;
    const int wm = (wid & 3) * 32;      // warp row offset (0..96)
    const int wn = (wid >> 2) * 32;     // warp col offset (0 or 32)
    uint32_t sb = smem_u32(smem);

    const __half* Axh = g_xh + ((size_t)b * N_ + i0) * D_;
    const __half* Byh = g_yh + ((size_t)b * M_ + j0) * D_;

    auto stage_load = [&](int c, int s) {
        uint32_t tb = sb + s * GS_STAGE;
        #pragma unroll
        for (int q = 0; q < 4; q++) {
            int idx = q * 256 + tid;            // A: 1024 chunks
            int row = idx >> 3, cc = idx & 7;
            uint32_t off = row * 128 + ((cc ^ (row & 7)) << 4);
            const __half* g = Axh + (size_t)row * D_ + c * 64 + cc * 8;
            CP_ASYNC16(tb + off, (const void*)__cvta_generic_to_global(g));
        }
        #pragma unroll
        for (int q = 0; q < 2; q++) {
            int idx = q * 256 + tid;            // B: 512 chunks
            int row = idx >> 3, cc = idx & 7;
            uint32_t off = row * 128 + ((cc ^ (row & 7)) << 4);
            const __half* g = Byh + (size_t)row * D_ + c * 64 + cc * 8;
            CP_ASYNC16(tb + 16384 + off, (const void*)__cvta_generic_to_global(g));
        }
    };

    float acc[2][4][4];
    #pragma unroll
    for (int mt = 0; mt < 2; mt++)
        #pragma unroll
        for (int nf = 0; nf < 4; nf++)
            #pragma unroll
            for (int q = 0; q < 4; q++) acc[mt][nf][q] = 0.f;

    stage_load(0, 0);
    CP_COMMIT();

    for (int c = 0; c < 8; c++) {
        if (c < 7) { stage_load(c + 1, (c + 1) & 1); CP_COMMIT(); CP_WAIT1(); }
        else       { CP_WAIT0(); }
        __syncthreads();

        uint32_t base = sb + (c & 1) * GS_STAGE;
        #pragma unroll
        for (int kk = 0; kk < 4; kk++) {
            uint32_t ah[2][4], bh[4][2];
            #pragma unroll
            for (int mt = 0; mt < 2; mt++) {
                int row = wm + mt * 16 + ((lane >> 3) & 1) * 8 + (lane & 7);
                int seg = kk * 2 + (lane >> 4);
                uint32_t ad = base + row * 128 + ((seg ^ (row & 7)) << 4);
                ldsm_x4(ah[mt][0], ah[mt][1], ah[mt][2], ah[mt][3], ad);
            }
            #pragma unroll
            for (int np = 0; np < 2; np++) {
                int row = wn + np * 16 + (lane >> 4) * 8 + (lane & 7);
                int seg = kk * 2 + ((lane >> 3) & 1);
                uint32_t ad = base + 16384 + row * 128 + ((seg ^ (row & 7)) << 4);
                ldsm_x4(bh[np*2][0], bh[np*2][1], bh[np*2+1][0], bh[np*2+1][1], ad);
            }
            #pragma unroll
            for (int mt = 0; mt < 2; mt++)
                #pragma unroll
                for (int nf = 0; nf < 4; nf++)
                    mma16816(acc[mt][nf], ah[mt], bh[nf]);
        }
        __syncthreads();
    }

    // epilogue: E = exp(-C/eps) -> bf16; stage E transposed in smem for ET.
    __nv_bfloat16* st16 = (__nv_bfloat16*)smem;   // 64 cols x ST_S = 17408 B
    #pragma unroll
    for (int mt = 0; mt < 2; mt++) {
        int lr0 = wm + mt * 16 + (lane >> 2);      // local row
        int r0 = i0 + lr0;
        float nx0 = g_nx[b * N_ + r0];
        float nx1 = g_nx[b * N_ + r0 + 8];
        #pragma unroll
        for (int nf = 0; nf < 4; nf++) {
            int lc0 = wn + nf * 8 + (lane & 3) * 2;
            int c0 = j0 + lc0;
            float ny0 = g_ny[b * M_ + c0];
            float ny1 = g_ny[b * M_ + c0 + 1];
            const float* a = acc[mt][nf];
            float C00 = 1.f - a[0] / fmaxf(nx0 * ny0, 1e-8f);
            float C01 = 1.f - a[1] / fmaxf(nx0 * ny1, 1e-8f);
            float C10 = 1.f - a[2] / fmaxf(nx1 * ny0, 1e-8f);
            float C11 = 1.f - a[3] / fmaxf(nx1 * ny1, 1e-8f);
            __nv_bfloat16 e00 = __float2bfloat16(__expf(-INV_EPS * C00));
            __nv_bfloat16 e01 = __float2bfloat16(__expf(-INV_EPS * C01));
            __nv_bfloat16 e10 = __float2bfloat16(__expf(-INV_EPS * C10));
            __nv_bfloat16 e11 = __float2bfloat16(__expf(-INV_EPS * C11));
            size_t ro0 = ((size_t)b * N_ + r0) * M_ + c0;
            size_t ro1 = ((size_t)b * N_ + r0 + 8) * M_ + c0;
            *(__nv_bfloat162*)(g_Ebf + ro0) = __halves2bfloat162(e00, e01);
            *(__nv_bfloat162*)(g_Ebf + ro1) = __halves2bfloat162(e10, e11);
            st16[lc0 * ST_S + lr0]           = e00;
            st16[(lc0 + 1) * ST_S + lr0]     = e01;
            st16[lc0 * ST_S + lr0 + 8]       = e10;
            st16[(lc0 + 1) * ST_S + lr0 + 8] = e11;
        }
    }
    __syncthreads();
    // ET tile: 64 rows (global cols j0..j0+63), each 128 bf16 at i0
    {
        int jj = tid >> 2;                  // 0..63
        int quarter = (tid & 3) * 32;       // 32 bf16 = 64 bytes
        __nv_bfloat16* dst = g_ETbf + ((size_t)b * M_ + j0 + jj) * N_ + i0 + quarter;
        const __nv_bfloat16* srcrow = st16 + jj * ST_S + quarter;
        #pragma unroll
        for (int k = 0; k < 32; k += 8)
            *(uint4*)(dst + k) = *(const uint4*)(srcrow + k);
    }
}

// ---------------- persistent Sinkhorn kernel (1024 threads/CTA) ----------------
// cooperative-groups-style grid sync: acq_rel atomic arrival + acquire poll.
__device__ __forceinline__ void grid_sync_dev() {
    __syncthreads();
    if (threadIdx.x == 0) {
        int gen;
        asm volatile("ld.global.s32 %0, [%1];" : "=r"(gen) : "l"(&g_gen) : "memory");
        int prev;
        asm volatile("atom.acq_rel.gpu.global.add.s32 %0, [%1], %2;"
                     : "=r"(prev) : "l"(&g_cnt), "r"(1) : "memory");
        if (prev == GRID_P - 1) {
            asm volatile("st.global.s32 [%0], %1;" :: "l"(&g_cnt), "r"(0) : "memory");
            asm volatile("st.release.gpu.global.s32 [%0], %1;"
                         :: "l"(&g_gen), "r"(gen + 1) : "memory");
        } else {
            int cur;
            do {
                asm volatile("ld.acquire.gpu.global.s32 %0, [%1];"
                             : "=r"(cur) : "l"(&g_gen) : "memory");
            } while (cur == gen);
        }
    }
    __syncthreads();
}

// dot over one bf16 row (1024 elems = 128 uint4) with fp32 weights
__device__ __forceinline__ float dot_bf_row(const uint4* erow, const float4* w, int lane) {
    float s = 0.f;
    #pragma unroll
    for (int p = 0; p < 4; p++) {
        uint4 e = erow[p * 32 + lane];
        float4 w0 = w[(p * 32 + lane) * 2];
        float4 w1 = w[(p * 32 + lane) * 2 + 1];
        float2 f0 = __bfloat1622float2(*(__nv_bfloat162*)&e.x);
        float2 f1 = __bfloat1622float2(*(__nv_bfloat162*)&e.y);
        float2 f2 = __bfloat1622float2(*(__nv_bfloat162*)&e.z);
        float2 f3 = __bfloat1622float2(*(__nv_bfloat162*)&e.w);
        s += f0.x * w0.x + f0.y * w0.y + f1.x * w0.z + f1.y * w0.w
           + f2.x * w1.x + f2.y * w1.y + f3.x * w1.z + f3.y * w1.w;
    }
    #pragma unroll
    for (int o = 16; o; o >>= 1) s += __shfl_down_sync(0xffffffffu, s, o);
    return s;
}

__global__ __launch_bounds__(SINK_T)
void sinkhorn_kernel(const float* __restrict__ nu, float* __restrict__ out) {
    const int t = threadIdx.x, wid = t >> 5, lane = t & 31;
    const int wgid = blockIdx.x * (SINK_T / 32) + wid;   // 0..SINK_W-1
    __shared__ float red[32];
    __shared__ float redfull[SINK_T];

    {   // init: v=0 -> bexp=1, u=0
        int gid = blockIdx.x * SINK_T + t;
        if (gid < B_ * M_) { g_bexp[gid] = 1.0f; g_u[gid] = 0.0f; }
    }
    grid_sync_dev();

    for (int it = 0; it < NITER; it++) {
        // ---- u update (~1 row per warp) ----
        for (int r = wgid; r < B_ * N_; r += SINK_W) {
            int b = r >> 10;
            float s = dot_bf_row((const uint4*)(g_Ebf + (size_t)r * M_),
                                 (const float4*)(g_bexp + (b << 10)), lane);
            if (lane == 0) {
                float u_new = EPS_F * (LOG_MU - __logf(s));
                g_errbuf[r] = fabsf(u_new - g_u[r]);
                g_u[r] = u_new;
                g_aexp[r] = MU_VAL / s;
            }
        }
        grid_sync_dev();   // publishes g_aexp AND g_errbuf

        // ---- err reduction (shuffle-based; identical in every CTA) ----
        float es = g_errbuf[t] + g_errbuf[t + 1024]
                 + g_errbuf[t + 2048] + g_errbuf[t + 3072];
        #pragma unroll
        for (int o = 16; o; o >>= 1) es += __shfl_down_sync(0xffffffffu, es, o);
        if (lane == 0) red[wid] = es;
        __syncthreads();
        if (wid == 0) {
            float v = red[lane];
            #pragma unroll
            for (int o = 16; o; o >>= 1) v += __shfl_down_sync(0xffffffffu, v, o);
            if (lane == 0) red[0] = v;
        }
        __syncthreads();
        float errv = red[0];

        // ---- v update ----
        for (int c = wgid; c < B_ * M_; c += SINK_W) {
            int b = c >> 10;
            float s = dot_bf_row((const uint4*)(g_ETbf + (size_t)c * N_),
                                 (const float4*)(g_aexp + (b << 10)), lane);
            if (lane == 0)
                g_bexp[c] = (__ldg(&nu[c]) + 1e-8f) / s;
        }
        grid_sync_dev();   // publishes g_bexp; fences errbuf from next writer

        // done-freeze: all remaining reference iterations are exact no-ops
        if (errv * 0.25f < THRESH_F) break;   // identical errv in all CTAs
    }

    // final cost: sum_i aexp_i * (sum_j E_ij*bexp_j*C_ij), C = -eps*ln(E)
    for (int r = wgid; r < B_ * N_; r += SINK_W) {
        int b = r >> 10;
        const uint4* erow = (const uint4*)(g_Ebf + (size_t)r * M_);
        const float4* w = (const float4*)(g_bexp + (b << 10));
        float s = 0.f;
        #pragma unroll
        for (int p = 0; p < 4; p++) {
            uint4 e = erow[p * 32 + lane];
            float4 w0 = w[(p * 32 + lane) * 2];
            float4 w1 = w[(p * 32 + lane) * 2 + 1];
            float2 f0 = __bfloat1622float2(*(__nv_bfloat162*)&e.x);
            float2 f1 = __bfloat1622float2(*(__nv_bfloat162*)&e.y);
            float2 f2 = __bfloat1622float2(*(__nv_bfloat162*)&e.z);
            float2 f3 = __bfloat1622float2(*(__nv_bfloat162*)&e.w);
            s += f0.x * w0.x * __logf(f0.x) + f0.y * w0.y * __logf(f0.y)
               + f1.x * w0.z * __logf(f1.x) + f1.y * w0.w * __logf(f1.y)
               + f2.x * w1.x * __logf(f2.x) + f2.y * w1.y * __logf(f2.y)
               + f3.x * w1.z * __logf(f3.x) + f3.y * w1.w * __logf(f3.y);
        }
        #pragma unroll
        for (int o = 16; o; o >>= 1) s += __shfl_down_sync(0xffffffffu, s, o);
        if (lane == 0) g_rowsum[r] = g_aexp[r] * s * (-EPS_F);
    }
    grid_sync_dev();
    if (blockIdx.x < B_) {
        int b = blockIdx.x;
        redfull[t] = g_rowsum[(b << 10) + t];
        __syncthreads();
        for (int o = 512; o; o >>= 1) {
            if (t < o) redfull[t] += redfull[t + o];
            __syncthreads();
        }
        if (t == 0) out[b] = redfull[0];
    }
}

// ---------------- launch ----------------
extern "C" void kernel_launch(void* const* d_in, const int* in_sizes, int n_in,
                              void* d_out, int out_size) {
    const float* x  = (const float*)d_in[0];
    const float* y  = (const float*)d_in[1];
    const float* nu = (const float*)d_in[2];
    float* out = (float*)d_out;

    cudaFuncSetAttribute(gemm_mma_kernel,
                         cudaFuncAttributeMaxDynamicSharedMemorySize, GEMM_SMEM);

    normsplit_kernel<<<512, 256>>>(x, y);

    gemm_mma_kernel<<<dim3(16, 8, 4), 256, GEMM_SMEM>>>();

    sinkhorn_kernel<<<GRID_P, SINK_T>>>(nu, out);
}